// round 6
// baseline (speedup 1.0000x reference)
#include <cuda_runtime.h>
#include <cuda_bf16.h>
#include <math.h>
#include <stdint.h>

#define NN      100000
#define EE      1600000
#define IN_DIM  256
#define HID     128
#define OUTD    64
#define LAYERS  3
#define LN_EPS  1e-5f

// ---------------- scratch (static device globals) ----------------
__device__ float g_h[(size_t)NN * HID];        // residual stream (fp32)
__device__ short g_xwq[(size_t)NN * HID];      // quantized conv output
__device__ float g_ws[NN];                     // per-row scale (incl. dinv[src])
__device__ int   g_cnt[NN];
__device__ int   g_cursor[NN];
__device__ float g_dinv[NN];
__device__ int   g_rowptr[NN + 1];
__device__ int   g_csr[EE];
__device__ int   g_bsum[1024];
// prepped weights: per 32-k chunk: [hi plane NC*40][lo plane NC*40], transposed [n][k], pad 8
__device__ __align__(16) __nv_bfloat16 g_wt[81920 + 3 * 40960 + 20480];

// ---------------- CSR build ----------------
__global__ void k_zero(void) {
    int i = blockIdx.x * blockDim.x + threadIdx.x;
    if (i < NN) { g_cnt[i] = 0; g_cursor[i] = 0; }
}
__global__ void k_count(const int* __restrict__ ei) {
    int i = blockIdx.x * blockDim.x + threadIdx.x;
    if (i < EE) atomicAdd(&g_cnt[ei[EE + i]], 1);
}
// scan (1024 elts/block) + fused dinv
__global__ void k_scan1(void) {
    __shared__ int sums[256];
    int t = threadIdx.x;
    int base = blockIdx.x * 1024 + t * 4;
    int v[4];
#pragma unroll
    for (int j = 0; j < 4; j++) v[j] = (base + j < NN) ? g_cnt[base + j] : 0;
#pragma unroll
    for (int j = 0; j < 4; j++)
        if (base + j < NN) g_dinv[base + j] = rsqrtf((float)(v[j] + 1));
    int tot = v[0] + v[1] + v[2] + v[3];
    sums[t] = tot;
    __syncthreads();
    for (int off = 1; off < 256; off <<= 1) {
        int x = 0;
        if (t >= off) x = sums[t - off];
        __syncthreads();
        if (t >= off) sums[t] += x;
        __syncthreads();
    }
    int run = sums[t] - tot;
#pragma unroll
    for (int j = 0; j < 4; j++) {
        if (base + j < NN) g_rowptr[base + j] = run;
        run += v[j];
    }
    if (t == 255) g_bsum[blockIdx.x] = sums[255];
}
__global__ void k_scan2(int nb) {
    __shared__ int sm[128];
    int t = threadIdx.x;
    int orig = (t < nb) ? g_bsum[t] : 0;
    sm[t] = orig;
    __syncthreads();
    for (int off = 1; off < 128; off <<= 1) {
        int x = 0;
        if (t >= off) x = sm[t - off];
        __syncthreads();
        if (t >= off) sm[t] += x;
        __syncthreads();
    }
    if (t < nb) g_bsum[t] = sm[t] - orig;
    if (t == 127) g_bsum[nb] = sm[127];
}
__global__ void k_scan3(int nb) {
    int i = blockIdx.x * blockDim.x + threadIdx.x;
    if (i < NN)       g_rowptr[i] += g_bsum[i >> 10];
    else if (i == NN) g_rowptr[NN] = g_bsum[nb];
}
__global__ void k_fill(const int* __restrict__ ei) {
    int i = blockIdx.x * blockDim.x + threadIdx.x;
    if (i < EE) {
        int d = ei[EE + i];
        int pos = g_rowptr[d] + atomicAdd(&g_cursor[d], 1);
        g_csr[pos] = ei[i];
    }
}

// ---------------- merged weight prep: transpose + bf16 hi/lo split ----------------
__device__ __forceinline__ void prep_one(const float* __restrict__ W,
                                         __nv_bfloat16* __restrict__ dst,
                                         int NC, int idx) {
    int k = idx / NC, n = idx % NC;
    int c = k >> 5, kk = k & 31;
    size_t base = (size_t)c * 2 * NC * 40;
    float v = W[idx];
    __nv_bfloat16 hb = __float2bfloat16(v);
    float lo = v - __bfloat162float(hb);
    dst[base + (size_t)n * 40 + kk] = hb;
    dst[base + (size_t)NC * 40 + (size_t)n * 40 + kk] = __float2bfloat16(lo);
}
__global__ void k_prep_all(const float* __restrict__ in_W,
                           const float* __restrict__ conv_W,
                           const float* __restrict__ out_W) {
    __nv_bfloat16* wt_in   = g_wt;
    __nv_bfloat16* wt_conv = g_wt + 81920;
    __nv_bfloat16* wt_out  = g_wt + 81920 + 3 * 40960;
    int idx = blockIdx.x * blockDim.x + threadIdx.x;
    constexpr int S_IN = IN_DIM * HID;              // 32768
    constexpr int S_CV = HID * HID;                 // 16384
    if (idx < S_IN) {
        prep_one(in_W, wt_in, HID, idx);
    } else if (idx < S_IN + 3 * S_CV) {
        int r = idx - S_IN;
        int l = r / S_CV, e = r % S_CV;
        prep_one(conv_W + (size_t)l * S_CV, wt_conv + (size_t)l * 40960, HID, e);
    } else if (idx < S_IN + 3 * S_CV + HID * OUTD) {
        int e = idx - S_IN - 3 * S_CV;
        prep_one(out_W, wt_out, OUTD, e);
    }
}

// ---------------- HMMA bf16 (3x split) GEMM ----------------
__device__ __forceinline__ void mma_bf16(float* d, const uint32_t* a, const uint32_t* b) {
    asm volatile(
        "mma.sync.aligned.m16n8k16.row.col.f32.bf16.bf16.f32 "
        "{%0,%1,%2,%3}, {%4,%5,%6,%7}, {%8,%9}, {%0,%1,%2,%3};"
        : "+f"(d[0]), "+f"(d[1]), "+f"(d[2]), "+f"(d[3])
        : "r"(a[0]), "r"(a[1]), "r"(a[2]), "r"(a[3]), "r"(b[0]), "r"(b[1]));
}

// C[M,NC] = A[M,K] @ W[K,NC].  CTA 128 x NC, 256 threads (8 warps: 4M x 2N).
// A-chunk register prefetch overlaps global load latency with MMA compute.
template <int K, int NC, bool QOUT>
__global__ void __launch_bounds__(256)
k_mma(const float* __restrict__ A, const __nv_bfloat16* __restrict__ Wsw,
      const float* __restrict__ bias, float* __restrict__ C, int M)
{
    constexpr int KC = 32, ST = 40;
    constexpr int WN = NC / 2;
    constexpr int NT = WN / 8;
    constexpr int NCHUNK = K / KC;
    extern __shared__ __align__(16) __nv_bfloat16 sm[];
    __nv_bfloat16* Ah = sm;                    // [128][40]
    __nv_bfloat16* Al = sm + 128 * ST;         // [128][40]
    __nv_bfloat16* Bs = sm + 2 * 128 * ST;     // [2][NC][40]

    int tid = threadIdx.x;
    int lane = tid & 31, wid = tid >> 5;
    int g = lane >> 2, tg = lane & 3;
    int wm = wid & 3, wn = wid >> 2;
    int row0 = blockIdx.x * 128;

    float acc[2][NT][4];
#pragma unroll
    for (int mt = 0; mt < 2; mt++)
#pragma unroll
        for (int nt = 0; nt < NT; nt++)
#pragma unroll
            for (int j = 0; j < 4; j++) acc[mt][nt][j] = 0.f;

    // per-thread A slot: 4 float4; row r = idx>>3, quad q = idx&7
    float4 pa[4];
    {
#pragma unroll
        for (int i = 0; i < 4; i++) {
            int idx = tid + i * 256;
            int r = idx >> 3, q = idx & 7;
            pa[i] = make_float4(0.f, 0.f, 0.f, 0.f);
            if (row0 + r < M) pa[i] = *(const float4*)(A + (size_t)(row0 + r) * K + q * 4);
        }
    }

    for (int c = 0; c < NCHUNK; c++) {
        // ---- store prefetched A chunk (convert to bf16 hi/lo) ----
#pragma unroll
        for (int i = 0; i < 4; i++) {
            int idx = tid + i * 256;
            int r = idx >> 3, q = idx & 7;
            float4 v = pa[i];
            __nv_bfloat16 hx = __float2bfloat16(v.x), hy = __float2bfloat16(v.y);
            __nv_bfloat16 hz = __float2bfloat16(v.z), hw = __float2bfloat16(v.w);
            __nv_bfloat162 h0; h0.x = hx; h0.y = hy;
            __nv_bfloat162 h1; h1.x = hz; h1.y = hw;
            __nv_bfloat162 l0, l1;
            l0.x = __float2bfloat16(v.x - __bfloat162float(hx));
            l0.y = __float2bfloat16(v.y - __bfloat162float(hy));
            l1.x = __float2bfloat16(v.z - __bfloat162float(hz));
            l1.y = __float2bfloat16(v.w - __bfloat162float(hw));
            int o = r * ST + q * 4;
            *(__nv_bfloat162*)(Ah + o)     = h0;
            *(__nv_bfloat162*)(Ah + o + 2) = h1;
            *(__nv_bfloat162*)(Al + o)     = l0;
            *(__nv_bfloat162*)(Al + o + 2) = l1;
        }
        // ---- B chunk: flat copy of prepped image ----
        {
            const float4* src = (const float4*)(Wsw + (size_t)c * 2 * NC * ST);
            float4* dst = (float4*)Bs;
            for (int i = tid; i < NC * 10; i += 256) dst[i] = src[i];
        }
        __syncthreads();

        // ---- prefetch next A chunk (overlaps with MMA below) ----
        if (c + 1 < NCHUNK) {
#pragma unroll
            for (int i = 0; i < 4; i++) {
                int idx = tid + i * 256;
                int r = idx >> 3, q = idx & 7;
                pa[i] = make_float4(0.f, 0.f, 0.f, 0.f);
                if (row0 + r < M)
                    pa[i] = *(const float4*)(A + (size_t)(row0 + r) * K + (c + 1) * KC + q * 4);
            }
        }

#pragma unroll
        for (int ks = 0; ks < 2; ks++) {
            int kof = ks * 16 + 2 * tg;
            uint32_t ah[2][4], al[2][4];
#pragma unroll
            for (int mt = 0; mt < 2; mt++) {
                int rb = wm * 32 + mt * 16 + g;
                ah[mt][0] = *(const uint32_t*)(Ah + rb * ST + kof);
                ah[mt][1] = *(const uint32_t*)(Ah + (rb + 8) * ST + kof);
                ah[mt][2] = *(const uint32_t*)(Ah + rb * ST + kof + 8);
                ah[mt][3] = *(const uint32_t*)(Ah + (rb + 8) * ST + kof + 8);
                al[mt][0] = *(const uint32_t*)(Al + rb * ST + kof);
                al[mt][1] = *(const uint32_t*)(Al + (rb + 8) * ST + kof);
                al[mt][2] = *(const uint32_t*)(Al + rb * ST + kof + 8);
                al[mt][3] = *(const uint32_t*)(Al + (rb + 8) * ST + kof + 8);
            }
            uint32_t bh[NT][2], bl[NT][2];
#pragma unroll
            for (int nt = 0; nt < NT; nt++) {
                int nb = wn * WN + nt * 8 + g;
                bh[nt][0] = *(const uint32_t*)(Bs + nb * ST + kof);
                bh[nt][1] = *(const uint32_t*)(Bs + nb * ST + kof + 8);
                bl[nt][0] = *(const uint32_t*)(Bs + NC * ST + nb * ST + kof);
                bl[nt][1] = *(const uint32_t*)(Bs + NC * ST + nb * ST + kof + 8);
            }
#pragma unroll
            for (int mt = 0; mt < 2; mt++)
#pragma unroll
                for (int nt = 0; nt < NT; nt++) {
                    mma_bf16(acc[mt][nt], ah[mt], bh[nt]);
                    mma_bf16(acc[mt][nt], ah[mt], bl[nt]);
                    mma_bf16(acc[mt][nt], al[mt], bh[nt]);
                }
        }
        __syncthreads();
    }

    if constexpr (QOUT) {
        // per-row absmax -> int16 quantize; scale folds dinv[row]
        float* rmaxsm = (float*)sm;   // [2][128], tiles dead after last sync
#pragma unroll
        for (int mt = 0; mt < 2; mt++)
#pragma unroll
            for (int h8 = 0; h8 < 2; h8++) {
                float mx = 0.f;
#pragma unroll
                for (int nt = 0; nt < NT; nt++) {
                    mx = fmaxf(mx, fabsf(acc[mt][nt][2 * h8]));
                    mx = fmaxf(mx, fabsf(acc[mt][nt][2 * h8 + 1]));
                }
                mx = fmaxf(mx, __shfl_xor_sync(0xffffffffu, mx, 1));
                mx = fmaxf(mx, __shfl_xor_sync(0xffffffffu, mx, 2));
                int rl = wm * 32 + mt * 16 + h8 * 8 + g;
                if (tg == 0) rmaxsm[wn * 128 + rl] = mx;
            }
        __syncthreads();
#pragma unroll
        for (int mt = 0; mt < 2; mt++)
#pragma unroll
            for (int h8 = 0; h8 < 2; h8++) {
                int rl = wm * 32 + mt * 16 + h8 * 8 + g;
                int grow = row0 + rl;
                if (grow >= M) continue;
                float rm = fmaxf(rmaxsm[rl], rmaxsm[128 + rl]);
                float sc = (rm > 1e-30f) ? 32767.f / rm : 0.f;
                if (wn == 0 && tg == 0)
                    g_ws[grow] = g_dinv[grow] * rm * (1.f / 32767.f);
#pragma unroll
                for (int nt = 0; nt < NT; nt++) {
                    int col = wn * WN + nt * 8 + 2 * tg;
                    short2 q;
                    q.x = (short)__float2int_rn(acc[mt][nt][2 * h8] * sc);
                    q.y = (short)__float2int_rn(acc[mt][nt][2 * h8 + 1] * sc);
                    *(short2*)(g_xwq + (size_t)grow * HID + col) = q;
                }
            }
    } else {
#pragma unroll
        for (int mt = 0; mt < 2; mt++) {
            int r = row0 + wm * 32 + mt * 16 + g;
#pragma unroll
            for (int nt = 0; nt < NT; nt++) {
                int col = wn * WN + nt * 8 + 2 * tg;
                float bx = 0.f, by = 0.f;
                if (bias) { bx = bias[col]; by = bias[col + 1]; }
                if (r < M) {
                    float2 o0 = make_float2(acc[mt][nt][0] + bx, acc[mt][nt][1] + by);
                    *(float2*)(C + (size_t)r * NC + col) = o0;
                }
                if (r + 8 < M) {
                    float2 o1 = make_float2(acc[mt][nt][2] + bx, acc[mt][nt][3] + by);
                    *(float2*)(C + (size_t)(r + 8) * NC + col) = o1;
                }
            }
        }
    }
}

// ---------------- fused aggregate (int16 gather) + LN + ReLU + residual ----------------
__global__ void __launch_bounds__(256)
k_agg_ln(const float* __restrict__ conv_b,
         const float* __restrict__ ln_g,
         const float* __restrict__ ln_b)
{
    int warp = (blockIdx.x * blockDim.x + threadIdx.x) >> 5;
    int lane = threadIdx.x & 31;
    if (warp >= NN) return;

    const short4* __restrict__ xq = (const short4*)g_xwq;
    int beg = g_rowptr[warp];
    int end = g_rowptr[warp + 1];

    float4 acc = make_float4(0.f, 0.f, 0.f, 0.f);
    int e = beg;
    for (; e + 4 <= end; e += 4) {
        int s0 = g_csr[e], s1 = g_csr[e + 1], s2 = g_csr[e + 2], s3 = g_csr[e + 3];
        float w0 = g_ws[s0], w1 = g_ws[s1], w2 = g_ws[s2], w3 = g_ws[s3];
        short4 v0 = xq[s0 * 32 + lane];
        short4 v1 = xq[s1 * 32 + lane];
        short4 v2 = xq[s2 * 32 + lane];
        short4 v3 = xq[s3 * 32 + lane];
        acc.x += w0 * (float)v0.x + w1 * (float)v1.x + w2 * (float)v2.x + w3 * (float)v3.x;
        acc.y += w0 * (float)v0.y + w1 * (float)v1.y + w2 * (float)v2.y + w3 * (float)v3.y;
        acc.z += w0 * (float)v0.z + w1 * (float)v1.z + w2 * (float)v2.z + w3 * (float)v3.z;
        acc.w += w0 * (float)v0.w + w1 * (float)v1.w + w2 * (float)v2.w + w3 * (float)v3.w;
    }
    for (; e < end; e++) {
        int s = g_csr[e];
        float w = g_ws[s];
        short4 v = xq[s * 32 + lane];
        acc.x += w * (float)v.x; acc.y += w * (float)v.y;
        acc.z += w * (float)v.z; acc.w += w * (float)v.w;
    }
    // self loop
    {
        float w = g_ws[warp];
        short4 v = xq[warp * 32 + lane];
        acc.x += w * (float)v.x; acc.y += w * (float)v.y;
        acc.z += w * (float)v.z; acc.w += w * (float)v.w;
    }
    float di = g_dinv[warp];
    acc.x *= di; acc.y *= di; acc.z *= di; acc.w *= di;

    float4 cb = ((const float4*)conv_b)[lane];
    acc.x += cb.x; acc.y += cb.y; acc.z += cb.z; acc.w += cb.w;

    float s = acc.x + acc.y + acc.z + acc.w;
#pragma unroll
    for (int off = 16; off > 0; off >>= 1) s += __shfl_xor_sync(0xffffffffu, s, off);
    float mu = s * (1.f / 128.f);
    float dx = acc.x - mu, dy = acc.y - mu, dz = acc.z - mu, dw = acc.w - mu;
    float q = dx * dx + dy * dy + dz * dz + dw * dw;
#pragma unroll
    for (int off = 16; off > 0; off >>= 1) q += __shfl_xor_sync(0xffffffffu, q, off);
    float rstd = rsqrtf(q * (1.f / 128.f) + LN_EPS);

    float4 lg = ((const float4*)ln_g)[lane];
    float4 lb = ((const float4*)ln_b)[lane];
    float4 y;
    y.x = fmaxf(dx * rstd * lg.x + lb.x, 0.f);
    y.y = fmaxf(dy * rstd * lg.y + lb.y, 0.f);
    y.z = fmaxf(dz * rstd * lg.z + lb.z, 0.f);
    y.w = fmaxf(dw * rstd * lg.w + lb.w, 0.f);

    float4* h4 = (float4*)g_h + warp * 32 + lane;
    float4 hv = *h4;
    hv.x += y.x; hv.y += y.y; hv.z += y.z; hv.w += y.w;
    *h4 = hv;
}

// ---------------------------------------------------------------------
extern "C" void kernel_launch(void* const* d_in, const int* in_sizes, int n_in,
                              void* d_out, int out_size)
{
    const float* x      = (const float*)d_in[0];
    const int*   ei     = (const int*)  d_in[1];
    const float* in_W   = (const float*)d_in[2];
    const float* in_b   = (const float*)d_in[3];
    const float* conv_W = (const float*)d_in[4];
    const float* conv_b = (const float*)d_in[5];
    const float* ln_g   = (const float*)d_in[6];
    const float* ln_b   = (const float*)d_in[7];
    const float* out_W  = (const float*)d_in[8];
    const float* out_b  = (const float*)d_in[9];
    float* out = (float*)d_out;

    float* h  = nullptr;  cudaGetSymbolAddress((void**)&h,  g_h);
    __nv_bfloat16* wt = nullptr;  cudaGetSymbolAddress((void**)&wt, g_wt);

    __nv_bfloat16* wt_in   = wt;
    __nv_bfloat16* wt_conv = wt + 81920;
    __nv_bfloat16* wt_out  = wt + 81920 + 3 * 40960;

    const int TB = 256;
    int nb_scan = (NN + 1023) / 1024;
    int gb = (NN + 127) / 128;
    constexpr int SM128 = (2 * 128 * 40 + 2 * 128 * 40) * 2;  // 40960 B
    constexpr int SM64  = (2 * 128 * 40 + 2 * 64 * 40) * 2;   // 30720 B
    constexpr int PREP_TOT = IN_DIM * HID + 3 * HID * HID + HID * OUTD;

    // 0: merged weight prep
    k_prep_all<<<(PREP_TOT + TB - 1) / TB, TB>>>(in_W, conv_W, out_W);
    // 1-2: degree count
    k_zero <<<(NN + TB - 1) / TB, TB>>>();
    k_count<<<(EE + TB - 1) / TB, TB>>>(ei);
    // 3: input projection (profiled slot)
    k_mma<IN_DIM, HID, false><<<gb, 256, SM128>>>(x, wt_in, in_b, h, NN);
    // 4-7: scan (+dinv) and CSR fill
    k_scan1<<<nb_scan, 256>>>();
    k_scan2<<<1, 128>>>(nb_scan);
    k_scan3<<<(NN + 1 + TB - 1) / TB, TB>>>(nb_scan);
    k_fill <<<(EE + TB - 1) / TB, TB>>>(ei);

    for (int l = 0; l < LAYERS; l++) {
        k_mma<HID, HID, true><<<gb, 256, SM128>>>(h, wt_conv + (size_t)l * 40960,
                                                  nullptr, nullptr, NN);
        k_agg_ln<<<(NN * 32 + TB - 1) / TB, TB>>>(conv_b + (size_t)l * HID,
                                                  ln_g + (size_t)l * HID,
                                                  ln_b + (size_t)l * HID);
    }

    // output projection
    k_mma<HID, OUTD, false><<<gb, 256, SM64>>>(h, wt_out, out_b, out, NN);
}

// round 7
// speedup vs baseline: 1.1243x; 1.1243x over previous
#include <cuda_runtime.h>
#include <cuda_bf16.h>
#include <math.h>
#include <stdint.h>

#define NN      100000
#define EE      1600000
#define IN_DIM  256
#define HID     128
#define OUTD    64
#define LAYERS  3
#define LN_EPS  1e-5f

// ---------------- scratch (static device globals) ----------------
__device__ float g_h[(size_t)NN * HID];        // residual stream (fp32)
__device__ short g_xwq[(size_t)NN * HID];      // quantized conv output
__device__ float g_ws[NN];                     // per-row scale (incl. dinv[src])
__device__ int   g_cnt[NN];
__device__ int   g_cursor[NN];
__device__ float g_dinv[NN];
__device__ int   g_rowptr[NN + 1];
__device__ int   g_csr[EE];
__device__ int   g_bsum[1024];
// prepped weights: per 32-k chunk: [hi plane NC*40][lo plane NC*40], transposed [n][k], pad 8
__device__ __align__(16) __nv_bfloat16 g_wt[81920 + 3 * 40960 + 20480];

// ---------------- CSR build ----------------
__global__ void k_zero(void) {
    int i = blockIdx.x * blockDim.x + threadIdx.x;
    if (i < NN) { g_cnt[i] = 0; g_cursor[i] = 0; }
}
__global__ void k_count(const int* __restrict__ ei) {
    int i = blockIdx.x * blockDim.x + threadIdx.x;
    if (i < EE) atomicAdd(&g_cnt[ei[EE + i]], 1);
}
// scan (1024 elts/block) + fused dinv
__global__ void k_scan1(void) {
    __shared__ int sums[256];
    int t = threadIdx.x;
    int base = blockIdx.x * 1024 + t * 4;
    int v[4];
#pragma unroll
    for (int j = 0; j < 4; j++) v[j] = (base + j < NN) ? g_cnt[base + j] : 0;
#pragma unroll
    for (int j = 0; j < 4; j++)
        if (base + j < NN) g_dinv[base + j] = rsqrtf((float)(v[j] + 1));
    int tot = v[0] + v[1] + v[2] + v[3];
    sums[t] = tot;
    __syncthreads();
    for (int off = 1; off < 256; off <<= 1) {
        int x = 0;
        if (t >= off) x = sums[t - off];
        __syncthreads();
        if (t >= off) sums[t] += x;
        __syncthreads();
    }
    int run = sums[t] - tot;
#pragma unroll
    for (int j = 0; j < 4; j++) {
        if (base + j < NN) g_rowptr[base + j] = run;
        run += v[j];
    }
    if (t == 255) g_bsum[blockIdx.x] = sums[255];
}
__global__ void k_scan2(int nb) {
    __shared__ int sm[128];
    int t = threadIdx.x;
    int orig = (t < nb) ? g_bsum[t] : 0;
    sm[t] = orig;
    __syncthreads();
    for (int off = 1; off < 128; off <<= 1) {
        int x = 0;
        if (t >= off) x = sm[t - off];
        __syncthreads();
        if (t >= off) sm[t] += x;
        __syncthreads();
    }
    if (t < nb) g_bsum[t] = sm[t] - orig;
    if (t == 127) g_bsum[nb] = sm[127];
}
__global__ void k_scan3(int nb) {
    int i = blockIdx.x * blockDim.x + threadIdx.x;
    if (i < NN)       g_rowptr[i] += g_bsum[i >> 10];
    else if (i == NN) g_rowptr[NN] = g_bsum[nb];
}
__global__ void k_fill(const int* __restrict__ ei) {
    int i = blockIdx.x * blockDim.x + threadIdx.x;
    if (i < EE) {
        int d = ei[EE + i];
        int pos = g_rowptr[d] + atomicAdd(&g_cursor[d], 1);
        g_csr[pos] = ei[i];
    }
}

// ---------------- merged weight prep: transpose + bf16 hi/lo split ----------------
__device__ __forceinline__ void prep_one(const float* __restrict__ W,
                                         __nv_bfloat16* __restrict__ dst,
                                         int NC, int idx) {
    int k = idx / NC, n = idx % NC;
    int c = k >> 5, kk = k & 31;
    size_t base = (size_t)c * 2 * NC * 40;
    float v = W[idx];
    __nv_bfloat16 hb = __float2bfloat16(v);
    float lo = v - __bfloat162float(hb);
    dst[base + (size_t)n * 40 + kk] = hb;
    dst[base + (size_t)NC * 40 + (size_t)n * 40 + kk] = __float2bfloat16(lo);
}
__global__ void k_prep_all(const float* __restrict__ in_W,
                           const float* __restrict__ conv_W,
                           const float* __restrict__ out_W) {
    __nv_bfloat16* wt_in   = g_wt;
    __nv_bfloat16* wt_conv = g_wt + 81920;
    __nv_bfloat16* wt_out  = g_wt + 81920 + 3 * 40960;
    int idx = blockIdx.x * blockDim.x + threadIdx.x;
    constexpr int S_IN = IN_DIM * HID;              // 32768
    constexpr int S_CV = HID * HID;                 // 16384
    if (idx < S_IN) {
        prep_one(in_W, wt_in, HID, idx);
    } else if (idx < S_IN + 3 * S_CV) {
        int r = idx - S_IN;
        int l = r / S_CV, e = r % S_CV;
        prep_one(conv_W + (size_t)l * S_CV, wt_conv + (size_t)l * 40960, HID, e);
    } else if (idx < S_IN + 3 * S_CV + HID * OUTD) {
        int e = idx - S_IN - 3 * S_CV;
        prep_one(out_W, wt_out, OUTD, e);
    }
}

// ---------------- HMMA bf16 (3x split) GEMM ----------------
__device__ __forceinline__ void mma_bf16(float* d, const uint32_t* a, const uint32_t* b) {
    asm volatile(
        "mma.sync.aligned.m16n8k16.row.col.f32.bf16.bf16.f32 "
        "{%0,%1,%2,%3}, {%4,%5,%6,%7}, {%8,%9}, {%0,%1,%2,%3};"
        : "+f"(d[0]), "+f"(d[1]), "+f"(d[2]), "+f"(d[3])
        : "r"(a[0]), "r"(a[1]), "r"(a[2]), "r"(a[3]), "r"(b[0]), "r"(b[1]));
}

// C[M,NC] = A[M,K] @ W[K,NC].  CTA 128 x NC, 256 threads (8 warps: 4M x 2N).
// __launch_bounds__(256, 2): cap at 128 regs so 2 CTAs/SM (16 warps) are resident.
template <int K, int NC, bool QOUT>
__global__ void __launch_bounds__(256, 2)
k_mma(const float* __restrict__ A, const __nv_bfloat16* __restrict__ Wsw,
      const float* __restrict__ bias, float* __restrict__ C, int M)
{
    constexpr int KC = 32, ST = 40;
    constexpr int WN = NC / 2;
    constexpr int NT = WN / 8;
    constexpr int NCHUNK = K / KC;
    extern __shared__ __align__(16) __nv_bfloat16 sm[];
    __nv_bfloat16* Ah = sm;                    // [128][40]
    __nv_bfloat16* Al = sm + 128 * ST;         // [128][40]
    __nv_bfloat16* Bs = sm + 2 * 128 * ST;     // [2][NC][40]

    int tid = threadIdx.x;
    int lane = tid & 31, wid = tid >> 5;
    int g = lane >> 2, tg = lane & 3;
    int wm = wid & 3, wn = wid >> 2;
    int row0 = blockIdx.x * 128;

    float acc[2][NT][4];
#pragma unroll
    for (int mt = 0; mt < 2; mt++)
#pragma unroll
        for (int nt = 0; nt < NT; nt++)
#pragma unroll
            for (int j = 0; j < 4; j++) acc[mt][nt][j] = 0.f;

    for (int c = 0; c < NCHUNK; c++) {
        // ---- A chunk: 128 rows x 32 k, fp32 -> bf16 hi/lo ----
        const float* Ac = A + (size_t)row0 * K + c * KC;
#pragma unroll
        for (int i = 0; i < 4; i++) {
            int idx = tid + i * 256;
            int r = idx >> 3, q = idx & 7;
            float4 v = make_float4(0.f, 0.f, 0.f, 0.f);
            if (row0 + r < M) v = *(const float4*)(Ac + (size_t)r * K + q * 4);
            __nv_bfloat16 hx = __float2bfloat16(v.x), hy = __float2bfloat16(v.y);
            __nv_bfloat16 hz = __float2bfloat16(v.z), hw = __float2bfloat16(v.w);
            __nv_bfloat162 h0; h0.x = hx; h0.y = hy;
            __nv_bfloat162 h1; h1.x = hz; h1.y = hw;
            __nv_bfloat162 l0, l1;
            l0.x = __float2bfloat16(v.x - __bfloat162float(hx));
            l0.y = __float2bfloat16(v.y - __bfloat162float(hy));
            l1.x = __float2bfloat16(v.z - __bfloat162float(hz));
            l1.y = __float2bfloat16(v.w - __bfloat162float(hw));
            int o = r * ST + q * 4;
            *(__nv_bfloat162*)(Ah + o)     = h0;
            *(__nv_bfloat162*)(Ah + o + 2) = h1;
            *(__nv_bfloat162*)(Al + o)     = l0;
            *(__nv_bfloat162*)(Al + o + 2) = l1;
        }
        // ---- B chunk: flat copy of prepped image ----
        {
            const float4* src = (const float4*)(Wsw + (size_t)c * 2 * NC * ST);
            float4* dst = (float4*)Bs;
            for (int i = tid; i < NC * 10; i += 256) dst[i] = src[i];
        }
        __syncthreads();

#pragma unroll
        for (int ks = 0; ks < 2; ks++) {
            int kof = ks * 16 + 2 * tg;
            uint32_t ah[2][4], al[2][4];
#pragma unroll
            for (int mt = 0; mt < 2; mt++) {
                int rb = wm * 32 + mt * 16 + g;
                ah[mt][0] = *(const uint32_t*)(Ah + rb * ST + kof);
                ah[mt][1] = *(const uint32_t*)(Ah + (rb + 8) * ST + kof);
                ah[mt][2] = *(const uint32_t*)(Ah + rb * ST + kof + 8);
                ah[mt][3] = *(const uint32_t*)(Ah + (rb + 8) * ST + kof + 8);
                al[mt][0] = *(const uint32_t*)(Al + rb * ST + kof);
                al[mt][1] = *(const uint32_t*)(Al + (rb + 8) * ST + kof);
                al[mt][2] = *(const uint32_t*)(Al + rb * ST + kof + 8);
                al[mt][3] = *(const uint32_t*)(Al + (rb + 8) * ST + kof + 8);
            }
            // B fragments loaded per-nt to keep live range (and reg count) small
#pragma unroll
            for (int nt = 0; nt < NT; nt++) {
                int nb = wn * WN + nt * 8 + g;
                uint32_t bh[2], bl[2];
                bh[0] = *(const uint32_t*)(Bs + nb * ST + kof);
                bh[1] = *(const uint32_t*)(Bs + nb * ST + kof + 8);
                bl[0] = *(const uint32_t*)(Bs + NC * ST + nb * ST + kof);
                bl[1] = *(const uint32_t*)(Bs + NC * ST + nb * ST + kof + 8);
#pragma unroll
                for (int mt = 0; mt < 2; mt++) {
                    mma_bf16(acc[mt][nt], ah[mt], bh);
                    mma_bf16(acc[mt][nt], ah[mt], bl);
                    mma_bf16(acc[mt][nt], al[mt], bh);
                }
            }
        }
        __syncthreads();
    }

    if constexpr (QOUT) {
        // per-row absmax -> int16 quantize; scale folds dinv[row]
        float* rmaxsm = (float*)sm;   // [2][128], tiles dead after last sync
#pragma unroll
        for (int mt = 0; mt < 2; mt++)
#pragma unroll
            for (int h8 = 0; h8 < 2; h8++) {
                float mx = 0.f;
#pragma unroll
                for (int nt = 0; nt < NT; nt++) {
                    mx = fmaxf(mx, fabsf(acc[mt][nt][2 * h8]));
                    mx = fmaxf(mx, fabsf(acc[mt][nt][2 * h8 + 1]));
                }
                mx = fmaxf(mx, __shfl_xor_sync(0xffffffffu, mx, 1));
                mx = fmaxf(mx, __shfl_xor_sync(0xffffffffu, mx, 2));
                int rl = wm * 32 + mt * 16 + h8 * 8 + g;
                if (tg == 0) rmaxsm[wn * 128 + rl] = mx;
            }
        __syncthreads();
#pragma unroll
        for (int mt = 0; mt < 2; mt++)
#pragma unroll
            for (int h8 = 0; h8 < 2; h8++) {
                int rl = wm * 32 + mt * 16 + h8 * 8 + g;
                int grow = row0 + rl;
                if (grow >= M) continue;
                float rm = fmaxf(rmaxsm[rl], rmaxsm[128 + rl]);
                float sc = (rm > 1e-30f) ? 32767.f / rm : 0.f;
                if (wn == 0 && tg == 0)
                    g_ws[grow] = g_dinv[grow] * rm * (1.f / 32767.f);
#pragma unroll
                for (int nt = 0; nt < NT; nt++) {
                    int col = wn * WN + nt * 8 + 2 * tg;
                    short2 q;
                    q.x = (short)__float2int_rn(acc[mt][nt][2 * h8] * sc);
                    q.y = (short)__float2int_rn(acc[mt][nt][2 * h8 + 1] * sc);
                    *(short2*)(g_xwq + (size_t)grow * HID + col) = q;
                }
            }
    } else {
#pragma unroll
        for (int mt = 0; mt < 2; mt++) {
            int r = row0 + wm * 32 + mt * 16 + g;
#pragma unroll
            for (int nt = 0; nt < NT; nt++) {
                int col = wn * WN + nt * 8 + 2 * tg;
                float bx = 0.f, by = 0.f;
                if (bias) { bx = bias[col]; by = bias[col + 1]; }
                if (r < M) {
                    float2 o0 = make_float2(acc[mt][nt][0] + bx, acc[mt][nt][1] + by);
                    *(float2*)(C + (size_t)r * NC + col) = o0;
                }
                if (r + 8 < M) {
                    float2 o1 = make_float2(acc[mt][nt][2] + bx, acc[mt][nt][3] + by);
                    *(float2*)(C + (size_t)(r + 8) * NC + col) = o1;
                }
            }
        }
    }
}

// ---------------- fused aggregate (int16 gather) + LN + ReLU + residual ----------------
__global__ void __launch_bounds__(256)
k_agg_ln(const float* __restrict__ conv_b,
         const float* __restrict__ ln_g,
         const float* __restrict__ ln_b)
{
    int warp = (blockIdx.x * blockDim.x + threadIdx.x) >> 5;
    int lane = threadIdx.x & 31;
    if (warp >= NN) return;

    const short4* __restrict__ xq = (const short4*)g_xwq;
    int beg = g_rowptr[warp];
    int end = g_rowptr[warp + 1];

    float4 acc = make_float4(0.f, 0.f, 0.f, 0.f);
    int e = beg;
    for (; e + 4 <= end; e += 4) {
        int s0 = g_csr[e], s1 = g_csr[e + 1], s2 = g_csr[e + 2], s3 = g_csr[e + 3];
        float w0 = g_ws[s0], w1 = g_ws[s1], w2 = g_ws[s2], w3 = g_ws[s3];
        short4 v0 = xq[s0 * 32 + lane];
        short4 v1 = xq[s1 * 32 + lane];
        short4 v2 = xq[s2 * 32 + lane];
        short4 v3 = xq[s3 * 32 + lane];
        acc.x += w0 * (float)v0.x + w1 * (float)v1.x + w2 * (float)v2.x + w3 * (float)v3.x;
        acc.y += w0 * (float)v0.y + w1 * (float)v1.y + w2 * (float)v2.y + w3 * (float)v3.y;
        acc.z += w0 * (float)v0.z + w1 * (float)v1.z + w2 * (float)v2.z + w3 * (float)v3.z;
        acc.w += w0 * (float)v0.w + w1 * (float)v1.w + w2 * (float)v2.w + w3 * (float)v3.w;
    }
    for (; e < end; e++) {
        int s = g_csr[e];
        float w = g_ws[s];
        short4 v = xq[s * 32 + lane];
        acc.x += w * (float)v.x; acc.y += w * (float)v.y;
        acc.z += w * (float)v.z; acc.w += w * (float)v.w;
    }
    // self loop
    {
        float w = g_ws[warp];
        short4 v = xq[warp * 32 + lane];
        acc.x += w * (float)v.x; acc.y += w * (float)v.y;
        acc.z += w * (float)v.z; acc.w += w * (float)v.w;
    }
    float di = g_dinv[warp];
    acc.x *= di; acc.y *= di; acc.z *= di; acc.w *= di;

    float4 cb = ((const float4*)conv_b)[lane];
    acc.x += cb.x; acc.y += cb.y; acc.z += cb.z; acc.w += cb.w;

    float s = acc.x + acc.y + acc.z + acc.w;
#pragma unroll
    for (int off = 16; off > 0; off >>= 1) s += __shfl_xor_sync(0xffffffffu, s, off);
    float mu = s * (1.f / 128.f);
    float dx = acc.x - mu, dy = acc.y - mu, dz = acc.z - mu, dw = acc.w - mu;
    float q = dx * dx + dy * dy + dz * dz + dw * dw;
#pragma unroll
    for (int off = 16; off > 0; off >>= 1) q += __shfl_xor_sync(0xffffffffu, q, off);
    float rstd = rsqrtf(q * (1.f / 128.f) + LN_EPS);

    float4 lg = ((const float4*)ln_g)[lane];
    float4 lb = ((const float4*)ln_b)[lane];
    float4 y;
    y.x = fmaxf(dx * rstd * lg.x + lb.x, 0.f);
    y.y = fmaxf(dy * rstd * lg.y + lb.y, 0.f);
    y.z = fmaxf(dz * rstd * lg.z + lb.z, 0.f);
    y.w = fmaxf(dw * rstd * lg.w + lb.w, 0.f);

    float4* h4 = (float4*)g_h + warp * 32 + lane;
    float4 hv = *h4;
    hv.x += y.x; hv.y += y.y; hv.z += y.z; hv.w += y.w;
    *h4 = hv;
}

// ---------------------------------------------------------------------
extern "C" void kernel_launch(void* const* d_in, const int* in_sizes, int n_in,
                              void* d_out, int out_size)
{
    const float* x      = (const float*)d_in[0];
    const int*   ei     = (const int*)  d_in[1];
    const float* in_W   = (const float*)d_in[2];
    const float* in_b   = (const float*)d_in[3];
    const float* conv_W = (const float*)d_in[4];
    const float* conv_b = (const float*)d_in[5];
    const float* ln_g   = (const float*)d_in[6];
    const float* ln_b   = (const float*)d_in[7];
    const float* out_W  = (const float*)d_in[8];
    const float* out_b  = (const float*)d_in[9];
    float* out = (float*)d_out;

    float* h  = nullptr;  cudaGetSymbolAddress((void**)&h,  g_h);
    __nv_bfloat16* wt = nullptr;  cudaGetSymbolAddress((void**)&wt, g_wt);

    __nv_bfloat16* wt_in   = wt;
    __nv_bfloat16* wt_conv = wt + 81920;
    __nv_bfloat16* wt_out  = wt + 81920 + 3 * 40960;

    const int TB = 256;
    int nb_scan = (NN + 1023) / 1024;
    int gb = (NN + 127) / 128;
    constexpr int SM128 = (2 * 128 * 40 + 2 * 128 * 40) * 2;  // 40960 B
    constexpr int SM64  = (2 * 128 * 40 + 2 * 64 * 40) * 2;   // 30720 B
    constexpr int PREP_TOT = IN_DIM * HID + 3 * HID * HID + HID * OUTD;

    // 0: merged weight prep
    k_prep_all<<<(PREP_TOT + TB - 1) / TB, TB>>>(in_W, conv_W, out_W);
    // 1-2: degree count
    k_zero <<<(NN + TB - 1) / TB, TB>>>();
    k_count<<<(EE + TB - 1) / TB, TB>>>(ei);
    // 3: input projection (profiled slot)
    k_mma<IN_DIM, HID, false><<<gb, 256, SM128>>>(x, wt_in, in_b, h, NN);
    // 4-7: scan (+dinv) and CSR fill
    k_scan1<<<nb_scan, 256>>>();
    k_scan2<<<1, 128>>>(nb_scan);
    k_scan3<<<(NN + 1 + TB - 1) / TB, TB>>>(nb_scan);
    k_fill <<<(EE + TB - 1) / TB, TB>>>(ei);

    for (int l = 0; l < LAYERS; l++) {
        k_mma<HID, HID, true><<<gb, 256, SM128>>>(h, wt_conv + (size_t)l * 40960,
                                                  nullptr, nullptr, NN);
        k_agg_ln<<<(NN * 32 + TB - 1) / TB, TB>>>(conv_b + (size_t)l * HID,
                                                  ln_g + (size_t)l * HID,
                                                  ln_b + (size_t)l * HID);
    }

    // output projection
    k_mma<HID, OUTD, false><<<gb, 256, SM64>>>(h, wt_out, out_b, out, NN);
}

// round 9
// speedup vs baseline: 1.1608x; 1.0325x over previous
#include <cuda_runtime.h>
#include <cuda_bf16.h>
#include <math.h>
#include <stdint.h>

#define NN      100000
#define EE      1600000
#define IN_DIM  256
#define HID     128
#define OUTD    64
#define LAYERS  3
#define LN_EPS  1e-5f

// ---------------- scratch (static device globals) ----------------
__device__ float g_h[(size_t)NN * HID];        // residual stream (fp32)
__device__ short g_xwq[(size_t)NN * HID];      // quantized conv output
__device__ float g_ws[NN];                     // per-row scale (incl. dinv[src])
__device__ int   g_cnt[NN];
__device__ int   g_cursor[NN];
__device__ float g_dinv[NN];
__device__ int   g_rowptr[NN + 1];
__device__ int   g_csr[EE];
__device__ int   g_bsum[1024];
// prepped weights: per 32-k chunk: [hi plane NC*40][lo plane NC*40], transposed [n][k], pad 8
__device__ __align__(16) __nv_bfloat16 g_wt[81920 + 3 * 40960 + 20480];

// ---------------- CSR build ----------------
__global__ void k_zero(void) {
    int i = blockIdx.x * blockDim.x + threadIdx.x;
    if (i < NN) { g_cnt[i] = 0; g_cursor[i] = 0; }
}
__global__ void k_count(const int* __restrict__ ei) {
    int i = blockIdx.x * blockDim.x + threadIdx.x;
    if (i < EE) atomicAdd(&g_cnt[ei[EE + i]], 1);
}
// scan (1024 elts/block) + fused dinv
__global__ void k_scan1(void) {
    __shared__ int sums[256];
    int t = threadIdx.x;
    int base = blockIdx.x * 1024 + t * 4;
    int v[4];
#pragma unroll
    for (int j = 0; j < 4; j++) v[j] = (base + j < NN) ? g_cnt[base + j] : 0;
#pragma unroll
    for (int j = 0; j < 4; j++)
        if (base + j < NN) g_dinv[base + j] = rsqrtf((float)(v[j] + 1));
    int tot = v[0] + v[1] + v[2] + v[3];
    sums[t] = tot;
    __syncthreads();
    for (int off = 1; off < 256; off <<= 1) {
        int x = 0;
        if (t >= off) x = sums[t - off];
        __syncthreads();
        if (t >= off) sums[t] += x;
        __syncthreads();
    }
    int run = sums[t] - tot;
#pragma unroll
    for (int j = 0; j < 4; j++) {
        if (base + j < NN) g_rowptr[base + j] = run;
        run += v[j];
    }
    if (t == 255) g_bsum[blockIdx.x] = sums[255];
}
__global__ void k_scan2(int nb) {
    __shared__ int sm[128];
    int t = threadIdx.x;
    int orig = (t < nb) ? g_bsum[t] : 0;
    sm[t] = orig;
    __syncthreads();
    for (int off = 1; off < 128; off <<= 1) {
        int x = 0;
        if (t >= off) x = sm[t - off];
        __syncthreads();
        if (t >= off) sm[t] += x;
        __syncthreads();
    }
    if (t < nb) g_bsum[t] = sm[t] - orig;
    if (t == 127) g_bsum[nb] = sm[127];
}
__global__ void k_scan3(int nb) {
    int i = blockIdx.x * blockDim.x + threadIdx.x;
    if (i < NN)       g_rowptr[i] += g_bsum[i >> 10];
    else if (i == NN) g_rowptr[NN] = g_bsum[nb];
}
__global__ void k_fill(const int* __restrict__ ei) {
    int i = blockIdx.x * blockDim.x + threadIdx.x;
    if (i < EE) {
        int d = ei[EE + i];
        int pos = g_rowptr[d] + atomicAdd(&g_cursor[d], 1);
        g_csr[pos] = ei[i];
    }
}

// ---------------- merged weight prep: transpose + bf16 hi/lo split ----------------
__device__ __forceinline__ void prep_one(const float* __restrict__ W,
                                         __nv_bfloat16* __restrict__ dst,
                                         int NC, int idx) {
    int k = idx / NC, n = idx % NC;
    int c = k >> 5, kk = k & 31;
    size_t base = (size_t)c * 2 * NC * 40;
    float v = W[idx];
    __nv_bfloat16 hb = __float2bfloat16(v);
    float lo = v - __bfloat162float(hb);
    dst[base + (size_t)n * 40 + kk] = hb;
    dst[base + (size_t)NC * 40 + (size_t)n * 40 + kk] = __float2bfloat16(lo);
}
__global__ void k_prep_all(const float* __restrict__ in_W,
                           const float* __restrict__ conv_W,
                           const float* __restrict__ out_W) {
    __nv_bfloat16* wt_in   = g_wt;
    __nv_bfloat16* wt_conv = g_wt + 81920;
    __nv_bfloat16* wt_out  = g_wt + 81920 + 3 * 40960;
    int idx = blockIdx.x * blockDim.x + threadIdx.x;
    constexpr int S_IN = IN_DIM * HID;              // 32768
    constexpr int S_CV = HID * HID;                 // 16384
    if (idx < S_IN) {
        prep_one(in_W, wt_in, HID, idx);
    } else if (idx < S_IN + 3 * S_CV) {
        int r = idx - S_IN;
        int l = r / S_CV, e = r % S_CV;
        prep_one(conv_W + (size_t)l * S_CV, wt_conv + (size_t)l * 40960, HID, e);
    } else if (idx < S_IN + 3 * S_CV + HID * OUTD) {
        int e = idx - S_IN - 3 * S_CV;
        prep_one(out_W, wt_out, OUTD, e);
    }
}

// ---------------- HMMA bf16 (3x split) GEMM ----------------
// NOT volatile: pure register op; lets ptxas interleave independent MMAs.
__device__ __forceinline__ void mma_bf16(float* d, const uint32_t* a, const uint32_t* b) {
    asm("mma.sync.aligned.m16n8k16.row.col.f32.bf16.bf16.f32 "
        "{%0,%1,%2,%3}, {%4,%5,%6,%7}, {%8,%9}, {%0,%1,%2,%3};"
        : "+f"(d[0]), "+f"(d[1]), "+f"(d[2]), "+f"(d[3])
        : "r"(a[0]), "r"(a[1]), "r"(a[2]), "r"(a[3]), "r"(b[0]), "r"(b[1]));
}

// C[M,NC] = A[M,K] @ W[K,NC].  CTA 128 x NC, 256 threads (8 warps: 4M x 2N).
template <int K, int NC, bool QOUT>
__global__ void __launch_bounds__(256, 2)
k_mma(const float* __restrict__ A, const __nv_bfloat16* __restrict__ Wsw,
      const float* __restrict__ bias, float* __restrict__ C, int M)
{
    constexpr int KC = 32, ST = 40;
    constexpr int WN = NC / 2;
    constexpr int NT = WN / 8;          // 8 (NC=128) or 4 (NC=64)
    constexpr int NH = (NT + 3) / 4;    // halves of 4 n-tiles
    constexpr int NCHUNK = K / KC;
    extern __shared__ __align__(16) __nv_bfloat16 sm[];
    __nv_bfloat16* Ah = sm;                    // [128][40]
    __nv_bfloat16* Al = sm + 128 * ST;         // [128][40]
    __nv_bfloat16* Bs = sm + 2 * 128 * ST;     // [2][NC][40]

    int tid = threadIdx.x;
    int lane = tid & 31, wid = tid >> 5;
    int g = lane >> 2, tg = lane & 3;
    int wm = wid & 3, wn = wid >> 2;
    int row0 = blockIdx.x * 128;

    float acc[2][NT][4];
#pragma unroll
    for (int mt = 0; mt < 2; mt++)
#pragma unroll
        for (int nt = 0; nt < NT; nt++)
#pragma unroll
            for (int j = 0; j < 4; j++) acc[mt][nt][j] = 0.f;

    for (int c = 0; c < NCHUNK; c++) {
        // ---- A chunk: 128 rows x 32 k, fp32 -> bf16 hi/lo ----
        const float* Ac = A + (size_t)row0 * K + c * KC;
#pragma unroll
        for (int i = 0; i < 4; i++) {
            int idx = tid + i * 256;
            int r = idx >> 3, q = idx & 7;
            float4 v = make_float4(0.f, 0.f, 0.f, 0.f);
            if (row0 + r < M) v = *(const float4*)(Ac + (size_t)r * K + q * 4);
            __nv_bfloat16 hx = __float2bfloat16(v.x), hy = __float2bfloat16(v.y);
            __nv_bfloat16 hz = __float2bfloat16(v.z), hw = __float2bfloat16(v.w);
            __nv_bfloat162 h0; h0.x = hx; h0.y = hy;
            __nv_bfloat162 h1; h1.x = hz; h1.y = hw;
            __nv_bfloat162 l0, l1;
            l0.x = __float2bfloat16(v.x - __bfloat162float(hx));
            l0.y = __float2bfloat16(v.y - __bfloat162float(hy));
            l1.x = __float2bfloat16(v.z - __bfloat162float(hz));
            l1.y = __float2bfloat16(v.w - __bfloat162float(hw));
            int o = r * ST + q * 4;
            *(__nv_bfloat162*)(Ah + o)     = h0;
            *(__nv_bfloat162*)(Ah + o + 2) = h1;
            *(__nv_bfloat162*)(Al + o)     = l0;
            *(__nv_bfloat162*)(Al + o + 2) = l1;
        }
        // ---- B chunk: flat copy of prepped image ----
        {
            const float4* src = (const float4*)(Wsw + (size_t)c * 2 * NC * ST);
            float4* dst = (float4*)Bs;
            for (int i = tid; i < NC * 10; i += 256) dst[i] = src[i];
        }
        __syncthreads();

#pragma unroll
        for (int ks = 0; ks < 2; ks++) {
            int kof = ks * 16 + 2 * tg;
            uint32_t ah[2][4], al[2][4];
#pragma unroll
            for (int mt = 0; mt < 2; mt++) {
                int rb = wm * 32 + mt * 16 + g;
                ah[mt][0] = *(const uint32_t*)(Ah + rb * ST + kof);
                ah[mt][1] = *(const uint32_t*)(Ah + (rb + 8) * ST + kof);
                ah[mt][2] = *(const uint32_t*)(Ah + rb * ST + kof + 8);
                ah[mt][3] = *(const uint32_t*)(Ah + (rb + 8) * ST + kof + 8);
                al[mt][0] = *(const uint32_t*)(Al + rb * ST + kof);
                al[mt][1] = *(const uint32_t*)(Al + (rb + 8) * ST + kof);
                al[mt][2] = *(const uint32_t*)(Al + rb * ST + kof + 8);
                al[mt][3] = *(const uint32_t*)(Al + (rb + 8) * ST + kof + 8);
            }
            // process n-tiles in halves of 4; within a half, issue MMAs grouped
            // by split term so accumulator-reuse distance is 8 (hides HMMA lat)
#pragma unroll
            for (int hf = 0; hf < NH; hf++) {
                uint32_t bh[4][2], bl[4][2];
#pragma unroll
                for (int j = 0; j < 4; j++) {
                    int nb = wn * WN + (hf * 4 + j) * 8 + g;
                    bh[j][0] = *(const uint32_t*)(Bs + nb * ST + kof);
                    bh[j][1] = *(const uint32_t*)(Bs + nb * ST + kof + 8);
                    bl[j][0] = *(const uint32_t*)(Bs + NC * ST + nb * ST + kof);
                    bl[j][1] = *(const uint32_t*)(Bs + NC * ST + nb * ST + kof + 8);
                }
#pragma unroll
                for (int mt = 0; mt < 2; mt++)
#pragma unroll
                    for (int j = 0; j < 4; j++)
                        mma_bf16(acc[mt][hf * 4 + j], ah[mt], bh[j]);
#pragma unroll
                for (int mt = 0; mt < 2; mt++)
#pragma unroll
                    for (int j = 0; j < 4; j++)
                        mma_bf16(acc[mt][hf * 4 + j], ah[mt], bl[j]);
#pragma unroll
                for (int mt = 0; mt < 2; mt++)
#pragma unroll
                    for (int j = 0; j < 4; j++)
                        mma_bf16(acc[mt][hf * 4 + j], al[mt], bh[j]);
            }
        }
        __syncthreads();
    }

    if constexpr (QOUT) {
        // per-row absmax -> int16 quantize; scale folds dinv[row]
        float* rmaxsm = (float*)sm;   // [2][128], tiles dead after last sync
#pragma unroll
        for (int mt = 0; mt < 2; mt++)
#pragma unroll
            for (int h8 = 0; h8 < 2; h8++) {
                float mx = 0.f;
#pragma unroll
                for (int nt = 0; nt < NT; nt++) {
                    mx = fmaxf(mx, fabsf(acc[mt][nt][2 * h8]));
                    mx = fmaxf(mx, fabsf(acc[mt][nt][2 * h8 + 1]));
                }
                mx = fmaxf(mx, __shfl_xor_sync(0xffffffffu, mx, 1));
                mx = fmaxf(mx, __shfl_xor_sync(0xffffffffu, mx, 2));
                int rl = wm * 32 + mt * 16 + h8 * 8 + g;
                if (tg == 0) rmaxsm[wn * 128 + rl] = mx;
            }
        __syncthreads();
#pragma unroll
        for (int mt = 0; mt < 2; mt++)
#pragma unroll
            for (int h8 = 0; h8 < 2; h8++) {
                int rl = wm * 32 + mt * 16 + h8 * 8 + g;
                int grow = row0 + rl;
                if (grow >= M) continue;
                float rm = fmaxf(rmaxsm[rl], rmaxsm[128 + rl]);
                float sc = (rm > 1e-30f) ? 32767.f / rm : 0.f;
                if (wn == 0 && tg == 0)
                    g_ws[grow] = g_dinv[grow] * rm * (1.f / 32767.f);
#pragma unroll
                for (int nt = 0; nt < NT; nt++) {
                    int col = wn * WN + nt * 8 + 2 * tg;
                    short2 q;
                    q.x = (short)__float2int_rn(acc[mt][nt][2 * h8] * sc);
                    q.y = (short)__float2int_rn(acc[mt][nt][2 * h8 + 1] * sc);
                    *(short2*)(g_xwq + (size_t)grow * HID + col) = q;
                }
            }
    } else {
#pragma unroll
        for (int mt = 0; mt < 2; mt++) {
            int r = row0 + wm * 32 + mt * 16 + g;
#pragma unroll
            for (int nt = 0; nt < NT; nt++) {
                int col = wn * WN + nt * 8 + 2 * tg;
                float bx = 0.f, by = 0.f;
                if (bias) { bx = bias[col]; by = bias[col + 1]; }
                if (r < M) {
                    float2 o0 = make_float2(acc[mt][nt][0] + bx, acc[mt][nt][1] + by);
                    *(float2*)(C + (size_t)r * NC + col) = o0;
                }
                if (r + 8 < M) {
                    float2 o1 = make_float2(acc[mt][nt][2] + bx, acc[mt][nt][3] + by);
                    *(float2*)(C + (size_t)(r + 8) * NC + col) = o1;
                }
            }
        }
    }
}

// ---------------- fused aggregate (int16 gather) + LN + ReLU + residual ----------------
__global__ void __launch_bounds__(256)
k_agg_ln(const float* __restrict__ conv_b,
         const float* __restrict__ ln_g,
         const float* __restrict__ ln_b)
{
    int warp = (blockIdx.x * blockDim.x + threadIdx.x) >> 5;
    int lane = threadIdx.x & 31;
    if (warp >= NN) return;

    const short4* __restrict__ xq = (const short4*)g_xwq;
    int beg = g_rowptr[warp];
    int end = g_rowptr[warp + 1];

    float4 acc = make_float4(0.f, 0.f, 0.f, 0.f);
    int e = beg;
    for (; e + 4 <= end; e += 4) {
        int s0 = g_csr[e], s1 = g_csr[e + 1], s2 = g_csr[e + 2], s3 = g_csr[e + 3];
        float w0 = g_ws[s0], w1 = g_ws[s1], w2 = g_ws[s2], w3 = g_ws[s3];
        short4 v0 = xq[s0 * 32 + lane];
        short4 v1 = xq[s1 * 32 + lane];
        short4 v2 = xq[s2 * 32 + lane];
        short4 v3 = xq[s3 * 32 + lane];
        acc.x += w0 * (float)v0.x + w1 * (float)v1.x + w2 * (float)v2.x + w3 * (float)v3.x;
        acc.y += w0 * (float)v0.y + w1 * (float)v1.y + w2 * (float)v2.y + w3 * (float)v3.y;
        acc.z += w0 * (float)v0.z + w1 * (float)v1.z + w2 * (float)v2.z + w3 * (float)v3.z;
        acc.w += w0 * (float)v0.w + w1 * (float)v1.w + w2 * (float)v2.w + w3 * (float)v3.w;
    }
    for (; e < end; e++) {
        int s = g_csr[e];
        float w = g_ws[s];
        short4 v = xq[s * 32 + lane];
        acc.x += w * (float)v.x; acc.y += w * (float)v.y;
        acc.z += w * (float)v.z; acc.w += w * (float)v.w;
    }
    // self loop
    {
        float w = g_ws[warp];
        short4 v = xq[warp * 32 + lane];
        acc.x += w * (float)v.x; acc.y += w * (float)v.y;
        acc.z += w * (float)v.z; acc.w += w * (float)v.w;
    }
    float di = g_dinv[warp];
    acc.x *= di; acc.y *= di; acc.z *= di; acc.w *= di;

    float4 cb = ((const float4*)conv_b)[lane];
    acc.x += cb.x; acc.y += cb.y; acc.z += cb.z; acc.w += cb.w;

    float s = acc.x + acc.y + acc.z + acc.w;
#pragma unroll
    for (int off = 16; off > 0; off >>= 1) s += __shfl_xor_sync(0xffffffffu, s, off);
    float mu = s * (1.f / 128.f);
    float dx = acc.x - mu, dy = acc.y - mu, dz = acc.z - mu, dw = acc.w - mu;
    float q = dx * dx + dy * dy + dz * dz + dw * dw;
#pragma unroll
    for (int off = 16; off > 0; off >>= 1) q += __shfl_xor_sync(0xffffffffu, q, off);
    float rstd = rsqrtf(q * (1.f / 128.f) + LN_EPS);

    float4 lg = ((const float4*)ln_g)[lane];
    float4 lb = ((const float4*)ln_b)[lane];
    float4 y;
    y.x = fmaxf(dx * rstd * lg.x + lb.x, 0.f);
    y.y = fmaxf(dy * rstd * lg.y + lb.y, 0.f);
    y.z = fmaxf(dz * rstd * lg.z + lb.z, 0.f);
    y.w = fmaxf(dw * rstd * lg.w + lb.w, 0.f);

    float4* h4 = (float4*)g_h + warp * 32 + lane;
    float4 hv = *h4;
    hv.x += y.x; hv.y += y.y; hv.z += y.z; hv.w += y.w;
    *h4 = hv;
}

// ---------------------------------------------------------------------
extern "C" void kernel_launch(void* const* d_in, const int* in_sizes, int n_in,
                              void* d_out, int out_size)
{
    const float* x      = (const float*)d_in[0];
    const int*   ei     = (const int*)  d_in[1];
    const float* in_W   = (const float*)d_in[2];
    const float* in_b   = (const float*)d_in[3];
    const float* conv_W = (const float*)d_in[4];
    const float* conv_b = (const float*)d_in[5];
    const float* ln_g   = (const float*)d_in[6];
    const float* ln_b   = (const float*)d_in[7];
    const float* out_W  = (const float*)d_in[8];
    const float* out_b  = (const float*)d_in[9];
    float* out = (float*)d_out;

    float* h  = nullptr;  cudaGetSymbolAddress((void**)&h,  g_h);
    __nv_bfloat16* wt = nullptr;  cudaGetSymbolAddress((void**)&wt, g_wt);

    __nv_bfloat16* wt_in   = wt;
    __nv_bfloat16* wt_conv = wt + 81920;
    __nv_bfloat16* wt_out  = wt + 81920 + 3 * 40960;

    const int TB = 256;
    int nb_scan = (NN + 1023) / 1024;
    int gb = (NN + 127) / 128;
    constexpr int SM128 = (2 * 128 * 40 + 2 * 128 * 40) * 2;  // 40960 B
    constexpr int SM64  = (2 * 128 * 40 + 2 * 64 * 40) * 2;   // 30720 B
    constexpr int PREP_TOT = IN_DIM * HID + 3 * HID * HID + HID * OUTD;

    // 0: merged weight prep
    k_prep_all<<<(PREP_TOT + TB - 1) / TB, TB>>>(in_W, conv_W, out_W);
    // 1-2: degree count
    k_zero <<<(NN + TB - 1) / TB, TB>>>();
    k_count<<<(EE + TB - 1) / TB, TB>>>(ei);
    // 3: input projection (profiled slot)
    k_mma<IN_DIM, HID, false><<<gb, 256, SM128>>>(x, wt_in, in_b, h, NN);
    // 4-7: scan (+dinv) and CSR fill
    k_scan1<<<nb_scan, 256>>>();
    k_scan2<<<1, 128>>>(nb_scan);
    k_scan3<<<(NN + 1 + TB - 1) / TB, TB>>>(nb_scan);
    k_fill <<<(EE + TB - 1) / TB, TB>>>(ei);

    for (int l = 0; l < LAYERS; l++) {
        k_mma<HID, HID, true><<<gb, 256, SM128>>>(h, wt_conv + (size_t)l * 40960,
                                                  nullptr, nullptr, NN);
        k_agg_ln<<<(NN * 32 + TB - 1) / TB, TB>>>(conv_b + (size_t)l * HID,
                                                  ln_g + (size_t)l * HID,
                                                  ln_b + (size_t)l * HID);
    }

    // output projection
    k_mma<HID, OUTD, false><<<gb, 256, SM64>>>(h, wt_out, out_b, out, NN);
}

// round 16
// speedup vs baseline: 1.3223x; 1.1391x over previous
#include <cuda_runtime.h>
#include <cuda_bf16.h>
#include <math.h>
#include <stdint.h>

#define NN      100000
#define EE      1600000
#define IN_DIM  256
#define HID     128
#define OUTD    64
#define LAYERS  3
#define LN_EPS  1e-5f

// ---------------- scratch (static device globals) ----------------
__device__ float g_h[(size_t)NN * HID];        // residual stream (fp32)
__device__ short g_xwq[(size_t)NN * HID];      // quantized conv output
__device__ float g_ws[NN];                     // per-row scale (incl. dinv[src])
__device__ int   g_cnt[NN];
__device__ int   g_cursor[NN];
__device__ float g_dinv[NN];
__device__ int   g_rowptr[NN + 1];
__device__ int   g_csr[EE];
__device__ int   g_bsum[1024];
// prepped weights: per 32-k chunk: [hi plane NC*40][lo plane NC*40], transposed [n][k], pad 8
__device__ __align__(16) __nv_bfloat16 g_wt[81920 + 3 * 40960 + 20480];

// ---------------- small PTX helpers ----------------
__device__ __forceinline__ uint32_t smem_u32(const void* p) {
    uint32_t a;
    asm("{ .reg .u64 t; cvta.to.shared.u64 t, %1; cvt.u32.u64 %0, t; }" : "=r"(a) : "l"(p));
    return a;
}
__device__ __forceinline__ void cp16(uint32_t dst, const void* src, int sz) {
    asm volatile("cp.async.cg.shared.global [%0], [%1], 16, %2;"
                 :: "r"(dst), "l"(src), "r"(sz));
}
#define CP_COMMIT() asm volatile("cp.async.commit_group;" ::: "memory")
#define CP_WAIT0()  asm volatile("cp.async.wait_group 0;" ::: "memory")

// ---------------- CSR build ----------------
__global__ void k_zero(void) {
    int i = blockIdx.x * blockDim.x + threadIdx.x;
    if (i < NN) { g_cnt[i] = 0; g_cursor[i] = 0; }
}
__global__ void k_count(const int* __restrict__ ei) {
    int i = blockIdx.x * blockDim.x + threadIdx.x;
    if (i < EE) atomicAdd(&g_cnt[ei[EE + i]], 1);
}
// scan (1024 elts/block) + fused dinv
__global__ void k_scan1(void) {
    __shared__ int sums[256];
    int t = threadIdx.x;
    int base = blockIdx.x * 1024 + t * 4;
    int v[4];
#pragma unroll
    for (int j = 0; j < 4; j++) v[j] = (base + j < NN) ? g_cnt[base + j] : 0;
#pragma unroll
    for (int j = 0; j < 4; j++)
        if (base + j < NN) g_dinv[base + j] = rsqrtf((float)(v[j] + 1));
    int tot = v[0] + v[1] + v[2] + v[3];
    sums[t] = tot;
    __syncthreads();
    for (int off = 1; off < 256; off <<= 1) {
        int x = 0;
        if (t >= off) x = sums[t - off];
        __syncthreads();
        if (t >= off) sums[t] += x;
        __syncthreads();
    }
    int run = sums[t] - tot;
#pragma unroll
    for (int j = 0; j < 4; j++) {
        if (base + j < NN) g_rowptr[base + j] = run;
        run += v[j];
    }
    if (t == 255) g_bsum[blockIdx.x] = sums[255];
}
__global__ void k_scan2(int nb) {
    __shared__ int sm[128];
    int t = threadIdx.x;
    int orig = (t < nb) ? g_bsum[t] : 0;
    sm[t] = orig;
    __syncthreads();
    for (int off = 1; off < 128; off <<= 1) {
        int x = 0;
        if (t >= off) x = sm[t - off];
        __syncthreads();
        if (t >= off) sm[t] += x;
        __syncthreads();
    }
    if (t < nb) g_bsum[t] = sm[t] - orig;
    if (t == 127) g_bsum[nb] = sm[127];
}
__global__ void k_scan3(int nb) {
    int i = blockIdx.x * blockDim.x + threadIdx.x;
    if (i < NN)       g_rowptr[i] += g_bsum[i >> 10];
    else if (i == NN) g_rowptr[NN] = g_bsum[nb];
}
__global__ void k_fill(const int* __restrict__ ei) {
    int i = blockIdx.x * blockDim.x + threadIdx.x;
    if (i < EE) {
        int d = ei[EE + i];
        int pos = g_rowptr[d] + atomicAdd(&g_cursor[d], 1);
        g_csr[pos] = ei[i];
    }
}

// ---------------- merged weight prep: transpose + bf16 hi/lo split ----------------
__device__ __forceinline__ void prep_one(const float* __restrict__ W,
                                         __nv_bfloat16* __restrict__ dst,
                                         int NC, int idx) {
    int k = idx / NC, n = idx % NC;
    int c = k >> 5, kk = k & 31;
    size_t base = (size_t)c * 2 * NC * 40;
    float v = W[idx];
    __nv_bfloat16 hb = __float2bfloat16(v);
    float lo = v - __bfloat162float(hb);
    dst[base + (size_t)n * 40 + kk] = hb;
    dst[base + (size_t)NC * 40 + (size_t)n * 40 + kk] = __float2bfloat16(lo);
}
__global__ void k_prep_all(const float* __restrict__ in_W,
                           const float* __restrict__ conv_W,
                           const float* __restrict__ out_W) {
    __nv_bfloat16* wt_in   = g_wt;
    __nv_bfloat16* wt_conv = g_wt + 81920;
    __nv_bfloat16* wt_out  = g_wt + 81920 + 3 * 40960;
    int idx = blockIdx.x * blockDim.x + threadIdx.x;
    constexpr int S_IN = IN_DIM * HID;              // 32768
    constexpr int S_CV = HID * HID;                 // 16384
    if (idx < S_IN) {
        prep_one(in_W, wt_in, HID, idx);
    } else if (idx < S_IN + 3 * S_CV) {
        int r = idx - S_IN;
        int l = r / S_CV, e = r % S_CV;
        prep_one(conv_W + (size_t)l * S_CV, wt_conv + (size_t)l * 40960, HID, e);
    } else if (idx < S_IN + 3 * S_CV + HID * OUTD) {
        int e = idx - S_IN - 3 * S_CV;
        prep_one(out_W, wt_out, OUTD, e);
    }
}

// ---------------- HMMA bf16 (3x split) GEMM ----------------
// NOT volatile: pure register op; lets ptxas interleave independent MMAs.
__device__ __forceinline__ void mma_bf16(float* d, const uint32_t* a, const uint32_t* b) {
    asm("mma.sync.aligned.m16n8k16.row.col.f32.bf16.bf16.f32 "
        "{%0,%1,%2,%3}, {%4,%5,%6,%7}, {%8,%9}, {%0,%1,%2,%3};"
        : "+f"(d[0]), "+f"(d[1]), "+f"(d[2]), "+f"(d[3])
        : "r"(a[0]), "r"(a[1]), "r"(a[2]), "r"(a[3]), "r"(b[0]), "r"(b[1]));
}

// C[M,NC] = A[M,K] @ W[K,NC].  CTA 128 x NC, 256 threads (8 warps: 4M x 2N).
// cp.async double-buffered pipeline: chunk c+1 (raw A + B) streams into SMEM
// while chunk c runs MMAs; fp32->bf16 hi/lo conversion is smem->smem.
template <int K, int NC, bool QOUT>
__global__ void __launch_bounds__(256, 2)
k_mma(const float* __restrict__ A, const __nv_bfloat16* __restrict__ Wsw,
      const float* __restrict__ bias, float* __restrict__ C, int M)
{
    constexpr int KC = 32, ST = 40;
    constexpr int WN = NC / 2;
    constexpr int NT = WN / 8;          // 8 (NC=128) or 4 (NC=64)
    constexpr int NH = (NT + 3) / 4;
    constexpr int NCHUNK = K / KC;
    constexpr int ABUF = 2 * 128 * ST * 2;   // Ah+Al bytes per buffer (20480)
    constexpr int BSZ  = 2 * NC * ST * 2;    // B bytes per buffer
    constexpr int OFF_B   = 2 * ABUF;
    constexpr int OFF_RAW = OFF_B + 2 * BSZ; // raw A fp32: 2 x 16384
    extern __shared__ __align__(16) char smc[];

    int tid = threadIdx.x;
    int lane = tid & 31, wid = tid >> 5;
    int g = lane >> 2, tg = lane & 3;
    int wm = wid & 3, wn = wid >> 2;
    int row0 = blockIdx.x * 128;

    uint32_t sb = smem_u32(smc);

    float acc[2][NT][4];
#pragma unroll
    for (int mt = 0; mt < 2; mt++)
#pragma unroll
        for (int nt = 0; nt < NT; nt++)
#pragma unroll
            for (int j = 0; j < 4; j++) acc[mt][nt][j] = 0.f;

    // ---- cp.async issue for chunk cc into buffer pb ----
    auto issue = [&](int cc, int pb) {
        const float* Ac = A + (size_t)row0 * K + cc * KC;
        uint32_t rawb = sb + OFF_RAW + pb * 16384;
#pragma unroll
        for (int i = 0; i < 4; i++) {
            int idx = tid + i * 256;
            int r = idx >> 3, q = idx & 7;
            bool ok = (row0 + r < M);
            const float* src = Ac + (ok ? ((size_t)r * K + q * 4) : 0);
            cp16(rawb + idx * 16, src, ok ? 16 : 0);
        }
        const char* bsrc = (const char*)(Wsw + (size_t)cc * 2 * NC * ST);
        uint32_t bb = sb + OFF_B + pb * BSZ;
        for (int i = tid; i < NC * 10; i += 256)
            cp16(bb + i * 16, bsrc + i * 16, 16);
        CP_COMMIT();
    };
    // ---- smem->smem convert raw fp32 -> bf16 hi/lo for buffer pb ----
    auto convert = [&](int pb) {
        const float4* raw = (const float4*)(smc + OFF_RAW + pb * 16384);
        __nv_bfloat16* Ah = (__nv_bfloat16*)(smc + pb * ABUF);
        __nv_bfloat16* Al = Ah + 128 * ST;
#pragma unroll
        for (int i = 0; i < 4; i++) {
            int idx = tid + i * 256;
            int r = idx >> 3, q = idx & 7;
            float4 v = raw[idx];
            __nv_bfloat16 hx = __float2bfloat16(v.x), hy = __float2bfloat16(v.y);
            __nv_bfloat16 hz = __float2bfloat16(v.z), hw = __float2bfloat16(v.w);
            __nv_bfloat162 h0; h0.x = hx; h0.y = hy;
            __nv_bfloat162 h1; h1.x = hz; h1.y = hw;
            __nv_bfloat162 l0, l1;
            l0.x = __float2bfloat16(v.x - __bfloat162float(hx));
            l0.y = __float2bfloat16(v.y - __bfloat162float(hy));
            l1.x = __float2bfloat16(v.z - __bfloat162float(hz));
            l1.y = __float2bfloat16(v.w - __bfloat162float(hw));
            int o = r * ST + q * 4;
            *(__nv_bfloat162*)(Ah + o)     = h0;
            *(__nv_bfloat162*)(Ah + o + 2) = h1;
            *(__nv_bfloat162*)(Al + o)     = l0;
            *(__nv_bfloat162*)(Al + o + 2) = l1;
        }
    };

    // prologue: stage + convert chunk 0
    issue(0, 0);
    CP_WAIT0();
    __syncthreads();
    convert(0);

    for (int c = 0; c < NCHUNK; c++) {
        int p = c & 1;
        __syncthreads();                       // conversion of chunk c visible
        if (c + 1 < NCHUNK) issue(c + 1, p ^ 1);

        const __nv_bfloat16* Ah = (const __nv_bfloat16*)(smc + p * ABUF);
        const __nv_bfloat16* Al = Ah + 128 * ST;
        const __nv_bfloat16* Bs = (const __nv_bfloat16*)(smc + OFF_B + p * BSZ);

#pragma unroll
        for (int ks = 0; ks < 2; ks++) {
            int kof = ks * 16 + 2 * tg;
            uint32_t ah[2][4], al[2][4];
#pragma unroll
            for (int mt = 0; mt < 2; mt++) {
                int rb = wm * 32 + mt * 16 + g;
                ah[mt][0] = *(const uint32_t*)(Ah + rb * ST + kof);
                ah[mt][1] = *(const uint32_t*)(Ah + (rb + 8) * ST + kof);
                ah[mt][2] = *(const uint32_t*)(Ah + rb * ST + kof + 8);
                ah[mt][3] = *(const uint32_t*)(Ah + (rb + 8) * ST + kof + 8);
                al[mt][0] = *(const uint32_t*)(Al + rb * ST + kof);
                al[mt][1] = *(const uint32_t*)(Al + (rb + 8) * ST + kof);
                al[mt][2] = *(const uint32_t*)(Al + rb * ST + kof + 8);
                al[mt][3] = *(const uint32_t*)(Al + (rb + 8) * ST + kof + 8);
            }
#pragma unroll
            for (int hf = 0; hf < NH; hf++) {
                uint32_t bh[4][2], bl[4][2];
#pragma unroll
                for (int j = 0; j < 4; j++) {
                    int nb = wn * WN + (hf * 4 + j) * 8 + g;
                    bh[j][0] = *(const uint32_t*)(Bs + nb * ST + kof);
                    bh[j][1] = *(const uint32_t*)(Bs + nb * ST + kof + 8);
                    bl[j][0] = *(const uint32_t*)(Bs + NC * ST + nb * ST + kof);
                    bl[j][1] = *(const uint32_t*)(Bs + NC * ST + nb * ST + kof + 8);
                }
#pragma unroll
                for (int mt = 0; mt < 2; mt++)
#pragma unroll
                    for (int j = 0; j < 4; j++)
                        mma_bf16(acc[mt][hf * 4 + j], ah[mt], bh[j]);
#pragma unroll
                for (int mt = 0; mt < 2; mt++)
#pragma unroll
                    for (int j = 0; j < 4; j++)
                        mma_bf16(acc[mt][hf * 4 + j], ah[mt], bl[j]);
#pragma unroll
                for (int mt = 0; mt < 2; mt++)
#pragma unroll
                    for (int j = 0; j < 4; j++)
                        mma_bf16(acc[mt][hf * 4 + j], al[mt], bh[j]);
            }
        }

        if (c + 1 < NCHUNK) {
            CP_WAIT0();
            __syncthreads();                   // cp.async data visible to all
            convert(p ^ 1);
        } else {
            __syncthreads();                   // MMA reads done before smem reuse
        }
    }

    if constexpr (QOUT) {
        // per-row absmax -> int16 quantize; scale folds dinv[row]
        float* rmaxsm = (float*)smc;   // [2][128], tiles dead after final sync
#pragma unroll
        for (int mt = 0; mt < 2; mt++)
#pragma unroll
            for (int h8 = 0; h8 < 2; h8++) {
                float mx = 0.f;
#pragma unroll
                for (int nt = 0; nt < NT; nt++) {
                    mx = fmaxf(mx, fabsf(acc[mt][nt][2 * h8]));
                    mx = fmaxf(mx, fabsf(acc[mt][nt][2 * h8 + 1]));
                }
                mx = fmaxf(mx, __shfl_xor_sync(0xffffffffu, mx, 1));
                mx = fmaxf(mx, __shfl_xor_sync(0xffffffffu, mx, 2));
                int rl = wm * 32 + mt * 16 + h8 * 8 + g;
                if (tg == 0) rmaxsm[wn * 128 + rl] = mx;
            }
        __syncthreads();
#pragma unroll
        for (int mt = 0; mt < 2; mt++)
#pragma unroll
            for (int h8 = 0; h8 < 2; h8++) {
                int rl = wm * 32 + mt * 16 + h8 * 8 + g;
                int grow = row0 + rl;
                if (grow >= M) continue;
                float rm = fmaxf(rmaxsm[rl], rmaxsm[128 + rl]);
                float sc = (rm > 1e-30f) ? 32767.f / rm : 0.f;
                if (wn == 0 && tg == 0)
                    g_ws[grow] = g_dinv[grow] * rm * (1.f / 32767.f);
#pragma unroll
                for (int nt = 0; nt < NT; nt++) {
                    int col = wn * WN + nt * 8 + 2 * tg;
                    short2 q;
                    q.x = (short)__float2int_rn(acc[mt][nt][2 * h8] * sc);
                    q.y = (short)__float2int_rn(acc[mt][nt][2 * h8 + 1] * sc);
                    *(short2*)(g_xwq + (size_t)grow * HID + col) = q;
                }
            }
    } else {
#pragma unroll
        for (int mt = 0; mt < 2; mt++) {
            int r = row0 + wm * 32 + mt * 16 + g;
#pragma unroll
            for (int nt = 0; nt < NT; nt++) {
                int col = wn * WN + nt * 8 + 2 * tg;
                float bx = 0.f, by = 0.f;
                if (bias) { bx = bias[col]; by = bias[col + 1]; }
                if (r < M) {
                    float2 o0 = make_float2(acc[mt][nt][0] + bx, acc[mt][nt][1] + by);
                    *(float2*)(C + (size_t)r * NC + col) = o0;
                }
                if (r + 8 < M) {
                    float2 o1 = make_float2(acc[mt][nt][2] + bx, acc[mt][nt][3] + by);
                    *(float2*)(C + (size_t)(r + 8) * NC + col) = o1;
                }
            }
        }
    }
}

// ---------------- fused aggregate (int16 gather) + LN + ReLU + residual ----------------
__global__ void __launch_bounds__(256)
k_agg_ln(const float* __restrict__ conv_b,
         const float* __restrict__ ln_g,
         const float* __restrict__ ln_b)
{
    int warp = (blockIdx.x * blockDim.x + threadIdx.x) >> 5;
    int lane = threadIdx.x & 31;
    if (warp >= NN) return;

    const short4* __restrict__ xq = (const short4*)g_xwq;
    int beg = g_rowptr[warp];
    int end = g_rowptr[warp + 1];

    float4 acc = make_float4(0.f, 0.f, 0.f, 0.f);
    int e = beg;
    for (; e + 4 <= end; e += 4) {
        int s0 = g_csr[e], s1 = g_csr[e + 1], s2 = g_csr[e + 2], s3 = g_csr[e + 3];
        float w0 = g_ws[s0], w1 = g_ws[s1], w2 = g_ws[s2], w3 = g_ws[s3];
        short4 v0 = xq[s0 * 32 + lane];
        short4 v1 = xq[s1 * 32 + lane];
        short4 v2 = xq[s2 * 32 + lane];
        short4 v3 = xq[s3 * 32 + lane];
        acc.x += w0 * (float)v0.x + w1 * (float)v1.x + w2 * (float)v2.x + w3 * (float)v3.x;
        acc.y += w0 * (float)v0.y + w1 * (float)v1.y + w2 * (float)v2.y + w3 * (float)v3.y;
        acc.z += w0 * (float)v0.z + w1 * (float)v1.z + w2 * (float)v2.z + w3 * (float)v3.z;
        acc.w += w0 * (float)v0.w + w1 * (float)v1.w + w2 * (float)v2.w + w3 * (float)v3.w;
    }
    for (; e < end; e++) {
        int s = g_csr[e];
        float w = g_ws[s];
        short4 v = xq[s * 32 + lane];
        acc.x += w * (float)v.x; acc.y += w * (float)v.y;
        acc.z += w * (float)v.z; acc.w += w * (float)v.w;
    }
    // self loop
    {
        float w = g_ws[warp];
        short4 v = xq[warp * 32 + lane];
        acc.x += w * (float)v.x; acc.y += w * (float)v.y;
        acc.z += w * (float)v.z; acc.w += w * (float)v.w;
    }
    float di = g_dinv[warp];
    acc.x *= di; acc.y *= di; acc.z *= di; acc.w *= di;

    float4 cb = ((const float4*)conv_b)[lane];
    acc.x += cb.x; acc.y += cb.y; acc.z += cb.z; acc.w += cb.w;

    float s = acc.x + acc.y + acc.z + acc.w;
#pragma unroll
    for (int off = 16; off > 0; off >>= 1) s += __shfl_xor_sync(0xffffffffu, s, off);
    float mu = s * (1.f / 128.f);
    float dx = acc.x - mu, dy = acc.y - mu, dz = acc.z - mu, dw = acc.w - mu;
    float q = dx * dx + dy * dy + dz * dz + dw * dw;
#pragma unroll
    for (int off = 16; off > 0; off >>= 1) q += __shfl_xor_sync(0xffffffffu, q, off);
    float rstd = rsqrtf(q * (1.f / 128.f) + LN_EPS);

    float4 lg = ((const float4*)ln_g)[lane];
    float4 lb = ((const float4*)ln_b)[lane];
    float4 y;
    y.x = fmaxf(dx * rstd * lg.x + lb.x, 0.f);
    y.y = fmaxf(dy * rstd * lg.y + lb.y, 0.f);
    y.z = fmaxf(dz * rstd * lg.z + lb.z, 0.f);
    y.w = fmaxf(dw * rstd * lg.w + lb.w, 0.f);

    float4* h4 = (float4*)g_h + warp * 32 + lane;
    float4 hv = *h4;
    hv.x += y.x; hv.y += y.y; hv.z += y.z; hv.w += y.w;
    *h4 = hv;
}

// ---------------------------------------------------------------------
extern "C" void kernel_launch(void* const* d_in, const int* in_sizes, int n_in,
                              void* d_out, int out_size)
{
    const float* x      = (const float*)d_in[0];
    const int*   ei     = (const int*)  d_in[1];
    const float* in_W   = (const float*)d_in[2];
    const float* in_b   = (const float*)d_in[3];
    const float* conv_W = (const float*)d_in[4];
    const float* conv_b = (const float*)d_in[5];
    const float* ln_g   = (const float*)d_in[6];
    const float* ln_b   = (const float*)d_in[7];
    const float* out_W  = (const float*)d_in[8];
    const float* out_b  = (const float*)d_in[9];
    float* out = (float*)d_out;

    float* h  = nullptr;  cudaGetSymbolAddress((void**)&h,  g_h);
    __nv_bfloat16* wt = nullptr;  cudaGetSymbolAddress((void**)&wt, g_wt);

    __nv_bfloat16* wt_in   = wt;
    __nv_bfloat16* wt_conv = wt + 81920;
    __nv_bfloat16* wt_out  = wt + 81920 + 3 * 40960;

    const int TB = 256;
    int nb_scan = (NN + 1023) / 1024;
    int gb = (NN + 127) / 128;
    // smem: AhAl[2] + B[2] + Araw[2]
    constexpr int SM128 = 2 * 20480 + 2 * 20480 + 2 * 16384;  // 114688
    constexpr int SM64  = 2 * 20480 + 2 * 10240 + 2 * 16384;  // 94208
    constexpr int PREP_TOT = IN_DIM * HID + 3 * HID * HID + HID * OUTD;

    cudaFuncSetAttribute(k_mma<IN_DIM, HID, false>,
                         cudaFuncAttributeMaxDynamicSharedMemorySize, SM128);
    cudaFuncSetAttribute(k_mma<HID, HID, true>,
                         cudaFuncAttributeMaxDynamicSharedMemorySize, SM128);
    cudaFuncSetAttribute(k_mma<HID, OUTD, false>,
                         cudaFuncAttributeMaxDynamicSharedMemorySize, SM64);

    // 0: merged weight prep
    k_prep_all<<<(PREP_TOT + TB - 1) / TB, TB>>>(in_W, conv_W, out_W);
    // 1-2: degree count
    k_zero <<<(NN + TB - 1) / TB, TB>>>();
    k_count<<<(EE + TB - 1) / TB, TB>>>(ei);
    // 3: input projection (profiled slot)
    k_mma<IN_DIM, HID, false><<<gb, 256, SM128>>>(x, wt_in, in_b, h, NN);
    // 4-7: scan (+dinv) and CSR fill
    k_scan1<<<nb_scan, 256>>>();
    k_scan2<<<1, 128>>>(nb_scan);
    k_scan3<<<(NN + 1 + TB - 1) / TB, TB>>>(nb_scan);
    k_fill <<<(EE + TB - 1) / TB, TB>>>(ei);

    for (int l = 0; l < LAYERS; l++) {
        k_mma<HID, HID, true><<<gb, 256, SM128>>>(h, wt_conv + (size_t)l * 40960,
                                                  nullptr, nullptr, NN);
        k_agg_ln<<<(NN * 32 + TB - 1) / TB, TB>>>(conv_b + (size_t)l * HID,
                                                  ln_g + (size_t)l * HID,
                                                  ln_b + (size_t)l * HID);
    }

    // output projection
    k_mma<HID, OUTD, false><<<gb, 256, SM64>>>(h, wt_out, out_b, out, NN);
}

// round 17
// speedup vs baseline: 1.3450x; 1.0172x over previous
#include <cuda_runtime.h>
#include <cuda_bf16.h>
#include <math.h>
#include <stdint.h>

#define NN      100000
#define EE      1600000
#define IN_DIM  256
#define HID     128
#define OUTD    64
#define LAYERS  3
#define LN_EPS  1e-5f

// ---------------- scratch (static device globals) ----------------
__device__ float g_h[(size_t)NN * HID];
__device__ short g_xwq[(size_t)NN * HID];
__device__ float g_ws[NN];
__device__ int   g_cnt[NN];
__device__ int   g_cursor[NN];
__device__ float g_dinv[NN];
__device__ int   g_rowptr[NN + 1];
__device__ int   g_csr[EE];
__device__ int   g_bsum[1024];
__device__ __align__(16) __nv_bfloat16 g_wt[81920 + 3 * 40960 + 20480];

// ---------------- small PTX helpers ----------------
__device__ __forceinline__ uint32_t smem_u32(const void* p) {
    uint32_t a;
    asm("{ .reg .u64 t; cvta.to.shared.u64 t, %1; cvt.u32.u64 %0, t; }" : "=r"(a) : "l"(p));
    return a;
}
__device__ __forceinline__ void cp16(uint32_t dst, const void* src, int sz) {
    asm volatile("cp.async.cg.shared.global [%0], [%1], 16, %2;"
                 :: "r"(dst), "l"(src), "r"(sz));
}
#define CP_COMMIT() asm volatile("cp.async.commit_group;" ::: "memory")
#define CP_WAIT0()  asm volatile("cp.async.wait_group 0;" ::: "memory")

__device__ __forceinline__ void ldsm_x4(uint32_t* r, uint32_t addr) {
    asm volatile("ldmatrix.sync.aligned.m8n8.x4.shared.b16 {%0,%1,%2,%3}, [%4];"
        : "=r"(r[0]), "=r"(r[1]), "=r"(r[2]), "=r"(r[3]) : "r"(addr));
}

// ---------------- CSR build ----------------
__global__ void k_zero(void) {
    int i = blockIdx.x * blockDim.x + threadIdx.x;
    if (i < NN) { g_cnt[i] = 0; g_cursor[i] = 0; }
}
__global__ void k_count(const int* __restrict__ ei) {
    int i = blockIdx.x * blockDim.x + threadIdx.x;
    if (i < EE) atomicAdd(&g_cnt[ei[EE + i]], 1);
}
__global__ void k_scan1(void) {
    __shared__ int sums[256];
    int t = threadIdx.x;
    int base = blockIdx.x * 1024 + t * 4;
    int v[4];
#pragma unroll
    for (int j = 0; j < 4; j++) v[j] = (base + j < NN) ? g_cnt[base + j] : 0;
#pragma unroll
    for (int j = 0; j < 4; j++)
        if (base + j < NN) g_dinv[base + j] = rsqrtf((float)(v[j] + 1));
    int tot = v[0] + v[1] + v[2] + v[3];
    sums[t] = tot;
    __syncthreads();
    for (int off = 1; off < 256; off <<= 1) {
        int x = 0;
        if (t >= off) x = sums[t - off];
        __syncthreads();
        if (t >= off) sums[t] += x;
        __syncthreads();
    }
    int run = sums[t] - tot;
#pragma unroll
    for (int j = 0; j < 4; j++) {
        if (base + j < NN) g_rowptr[base + j] = run;
        run += v[j];
    }
    if (t == 255) g_bsum[blockIdx.x] = sums[255];
}
__global__ void k_scan2(int nb) {
    __shared__ int sm[128];
    int t = threadIdx.x;
    int orig = (t < nb) ? g_bsum[t] : 0;
    sm[t] = orig;
    __syncthreads();
    for (int off = 1; off < 128; off <<= 1) {
        int x = 0;
        if (t >= off) x = sm[t - off];
        __syncthreads();
        if (t >= off) sm[t] += x;
        __syncthreads();
    }
    if (t < nb) g_bsum[t] = sm[t] - orig;
    if (t == 127) g_bsum[nb] = sm[127];
}
__global__ void k_scan3(int nb) {
    int i = blockIdx.x * blockDim.x + threadIdx.x;
    if (i < NN)       g_rowptr[i] += g_bsum[i >> 10];
    else if (i == NN) g_rowptr[NN] = g_bsum[nb];
}
__global__ void k_fill(const int* __restrict__ ei) {
    int i = blockIdx.x * blockDim.x + threadIdx.x;
    if (i < EE) {
        int d = ei[EE + i];
        int pos = g_rowptr[d] + atomicAdd(&g_cursor[d], 1);
        g_csr[pos] = ei[i];
    }
}

// ---------------- merged weight prep ----------------
__device__ __forceinline__ void prep_one(const float* __restrict__ W,
                                         __nv_bfloat16* __restrict__ dst,
                                         int NC, int idx) {
    int k = idx / NC, n = idx % NC;
    int c = k >> 5, kk = k & 31;
    size_t base = (size_t)c * 2 * NC * 40;
    float v = W[idx];
    __nv_bfloat16 hb = __float2bfloat16(v);
    float lo = v - __bfloat162float(hb);
    dst[base + (size_t)n * 40 + kk] = hb;
    dst[base + (size_t)NC * 40 + (size_t)n * 40 + kk] = __float2bfloat16(lo);
}
__global__ void k_prep_all(const float* __restrict__ in_W,
                           const float* __restrict__ conv_W,
                           const float* __restrict__ out_W) {
    __nv_bfloat16* wt_in   = g_wt;
    __nv_bfloat16* wt_conv = g_wt + 81920;
    __nv_bfloat16* wt_out  = g_wt + 81920 + 3 * 40960;
    int idx = blockIdx.x * blockDim.x + threadIdx.x;
    constexpr int S_IN = IN_DIM * HID;
    constexpr int S_CV = HID * HID;
    if (idx < S_IN) {
        prep_one(in_W, wt_in, HID, idx);
    } else if (idx < S_IN + 3 * S_CV) {
        int r = idx - S_IN;
        int l = r / S_CV, e = r % S_CV;
        prep_one(conv_W + (size_t)l * S_CV, wt_conv + (size_t)l * 40960, HID, e);
    } else if (idx < S_IN + 3 * S_CV + HID * OUTD) {
        int e = idx - S_IN - 3 * S_CV;
        prep_one(out_W, wt_out, OUTD, e);
    }
}

// ---------------- HMMA bf16 (3x split) GEMM ----------------
__device__ __forceinline__ void mma_bf16(float* d, const uint32_t* a, const uint32_t* b) {
    asm("mma.sync.aligned.m16n8k16.row.col.f32.bf16.bf16.f32 "
        "{%0,%1,%2,%3}, {%4,%5,%6,%7}, {%8,%9}, {%0,%1,%2,%3};"
        : "+f"(d[0]), "+f"(d[1]), "+f"(d[2]), "+f"(d[3])
        : "r"(a[0]), "r"(a[1]), "r"(a[2]), "r"(a[3]), "r"(b[0]), "r"(b[1]));
}

// C[M,NC] = A[M,K] @ W[K,NC].  CTA 128 x NC, 256 threads (8 warps: 4M x 2N).
// cp.async double-buffered pipeline + ldmatrix fragment loads.
template <int K, int NC, bool QOUT>
__global__ void __launch_bounds__(256, 2)
k_mma(const float* __restrict__ A, const __nv_bfloat16* __restrict__ Wsw,
      const float* __restrict__ bias, float* __restrict__ C, int M)
{
    constexpr int KC = 32, ST = 40;
    constexpr int WN = NC / 2;
    constexpr int NT = WN / 8;          // 8 (NC=128) or 4 (NC=64)
    constexpr int NH = (NT + 3) / 4;
    constexpr int NCHUNK = K / KC;
    constexpr int ABUF = 2 * 128 * ST * 2;   // 20480 B (hi+lo A planes)
    constexpr int BSZ  = 2 * NC * ST * 2;
    constexpr int OFF_B   = 2 * ABUF;
    constexpr int OFF_RAW = OFF_B + 2 * BSZ;
    extern __shared__ __align__(16) char smc[];

    int tid = threadIdx.x;
    int lane = tid & 31, wid = tid >> 5;
    int g = lane >> 2, tg = lane & 3;
    int wm = wid & 3, wn = wid >> 2;
    int row0 = blockIdx.x * 128;

    uint32_t sb = smem_u32(smc);

    // ldmatrix lane-address components
    int lt = lane >> 3;                              // tile index 0..3
    int a_roff = ((lt & 1) << 3) + (lane & 7);       // A: +8 rows for odd tiles
    int a_koff = (lt & 2) << 2;                      // A: +8 cols for tiles 2,3
    int b_jsel = lt >> 1;                            // B: second j for tiles 2,3
    int b_koff = (lt & 1) << 3;                      // B: +8 cols for odd tiles
    int b_nlane = lane & 7;

    float acc[2][NT][4];
#pragma unroll
    for (int mt = 0; mt < 2; mt++)
#pragma unroll
        for (int nt = 0; nt < NT; nt++)
#pragma unroll
            for (int j = 0; j < 4; j++) acc[mt][nt][j] = 0.f;

    auto issue = [&](int cc, int pb) {
        const float* Ac = A + (size_t)row0 * K + cc * KC;
        uint32_t rawb = sb + OFF_RAW + pb * 16384;
#pragma unroll
        for (int i = 0; i < 4; i++) {
            int idx = tid + i * 256;
            int r = idx >> 3, q = idx & 7;
            bool ok = (row0 + r < M);
            const float* src = Ac + (ok ? ((size_t)r * K + q * 4) : 0);
            cp16(rawb + idx * 16, src, ok ? 16 : 0);
        }
        const char* bsrc = (const char*)(Wsw + (size_t)cc * 2 * NC * ST);
        uint32_t bb = sb + OFF_B + pb * BSZ;
        for (int i = tid; i < NC * 10; i += 256)
            cp16(bb + i * 16, bsrc + i * 16, 16);
        CP_COMMIT();
    };
    auto convert = [&](int pb) {
        const float4* raw = (const float4*)(smc + OFF_RAW + pb * 16384);
        __nv_bfloat16* Ah = (__nv_bfloat16*)(smc + pb * ABUF);
        __nv_bfloat16* Al = Ah + 128 * ST;
#pragma unroll
        for (int i = 0; i < 4; i++) {
            int idx = tid + i * 256;
            int r = idx >> 3, q = idx & 7;
            float4 v = raw[idx];
            __nv_bfloat16 hx = __float2bfloat16(v.x), hy = __float2bfloat16(v.y);
            __nv_bfloat16 hz = __float2bfloat16(v.z), hw = __float2bfloat16(v.w);
            __nv_bfloat162 h0; h0.x = hx; h0.y = hy;
            __nv_bfloat162 h1; h1.x = hz; h1.y = hw;
            __nv_bfloat162 l0, l1;
            l0.x = __float2bfloat16(v.x - __bfloat162float(hx));
            l0.y = __float2bfloat16(v.y - __bfloat162float(hy));
            l1.x = __float2bfloat16(v.z - __bfloat162float(hz));
            l1.y = __float2bfloat16(v.w - __bfloat162float(hw));
            int o = r * ST + q * 4;
            *(__nv_bfloat162*)(Ah + o)     = h0;
            *(__nv_bfloat162*)(Ah + o + 2) = h1;
            *(__nv_bfloat162*)(Al + o)     = l0;
            *(__nv_bfloat162*)(Al + o + 2) = l1;
        }
    };

    issue(0, 0);
    CP_WAIT0();
    __syncthreads();
    convert(0);

    for (int c = 0; c < NCHUNK; c++) {
        int p = c & 1;
        __syncthreads();
        if (c + 1 < NCHUNK) issue(c + 1, p ^ 1);

        uint32_t aH = sb + p * ABUF;                 // Ah plane base (bytes)
        uint32_t aL = aH + 128 * ST * 2;             // Al plane
        uint32_t bH = sb + OFF_B + p * BSZ;          // B hi plane
        uint32_t bL = bH + NC * ST * 2;              // B lo plane

#pragma unroll
        for (int ks = 0; ks < 2; ks++) {
            int kb = ks * 16;
            uint32_t ah[2][4], al[2][4];
#pragma unroll
            for (int mt = 0; mt < 2; mt++) {
                uint32_t ao = (uint32_t)((wm * 32 + mt * 16 + a_roff) * ST + kb + a_koff) * 2;
                ldsm_x4(ah[mt], aH + ao);
                ldsm_x4(al[mt], aL + ao);
            }
#pragma unroll
            for (int hf = 0; hf < NH; hf++) {
                uint32_t bh[4][2], bl[4][2];
#pragma unroll
                for (int pr = 0; pr < 2; pr++) {     // j pairs (0,1) and (2,3)
                    int jp = hf * 4 + pr * 2;
                    uint32_t bo = (uint32_t)((wn * WN + (jp + b_jsel) * 8 + b_nlane) * ST
                                             + kb + b_koff) * 2;
                    ldsm_x4(&bh[pr * 2][0], bH + bo);
                    ldsm_x4(&bl[pr * 2][0], bL + bo);
                }
#pragma unroll
                for (int mt = 0; mt < 2; mt++)
#pragma unroll
                    for (int j = 0; j < 4; j++)
                        mma_bf16(acc[mt][hf * 4 + j], ah[mt], bh[j]);
#pragma unroll
                for (int mt = 0; mt < 2; mt++)
#pragma unroll
                    for (int j = 0; j < 4; j++)
                        mma_bf16(acc[mt][hf * 4 + j], ah[mt], bl[j]);
#pragma unroll
                for (int mt = 0; mt < 2; mt++)
#pragma unroll
                    for (int j = 0; j < 4; j++)
                        mma_bf16(acc[mt][hf * 4 + j], al[mt], bh[j]);
            }
        }

        if (c + 1 < NCHUNK) {
            CP_WAIT0();
            __syncthreads();
            convert(p ^ 1);
        } else {
            __syncthreads();
        }
    }

    if constexpr (QOUT) {
        float* rmaxsm = (float*)smc;
#pragma unroll
        for (int mt = 0; mt < 2; mt++)
#pragma unroll
            for (int h8 = 0; h8 < 2; h8++) {
                float mx = 0.f;
#pragma unroll
                for (int nt = 0; nt < NT; nt++) {
                    mx = fmaxf(mx, fabsf(acc[mt][nt][2 * h8]));
                    mx = fmaxf(mx, fabsf(acc[mt][nt][2 * h8 + 1]));
                }
                mx = fmaxf(mx, __shfl_xor_sync(0xffffffffu, mx, 1));
                mx = fmaxf(mx, __shfl_xor_sync(0xffffffffu, mx, 2));
                int rl = wm * 32 + mt * 16 + h8 * 8 + g;
                if (tg == 0) rmaxsm[wn * 128 + rl] = mx;
            }
        __syncthreads();
#pragma unroll
        for (int mt = 0; mt < 2; mt++)
#pragma unroll
            for (int h8 = 0; h8 < 2; h8++) {
                int rl = wm * 32 + mt * 16 + h8 * 8 + g;
                int grow = row0 + rl;
                if (grow >= M) continue;
                float rm = fmaxf(rmaxsm[rl], rmaxsm[128 + rl]);
                float sc = (rm > 1e-30f) ? 32767.f / rm : 0.f;
                if (wn == 0 && tg == 0)
                    g_ws[grow] = g_dinv[grow] * rm * (1.f / 32767.f);
#pragma unroll
                for (int nt = 0; nt < NT; nt++) {
                    int col = wn * WN + nt * 8 + 2 * tg;
                    short2 q;
                    q.x = (short)__float2int_rn(acc[mt][nt][2 * h8] * sc);
                    q.y = (short)__float2int_rn(acc[mt][nt][2 * h8 + 1] * sc);
                    *(short2*)(g_xwq + (size_t)grow * HID + col) = q;
                }
            }
    } else {
#pragma unroll
        for (int mt = 0; mt < 2; mt++) {
            int r = row0 + wm * 32 + mt * 16 + g;
#pragma unroll
            for (int nt = 0; nt < NT; nt++) {
                int col = wn * WN + nt * 8 + 2 * tg;
                float bx = 0.f, by = 0.f;
                if (bias) { bx = bias[col]; by = bias[col + 1]; }
                if (r < M) {
                    float2 o0 = make_float2(acc[mt][nt][0] + bx, acc[mt][nt][1] + by);
                    *(float2*)(C + (size_t)r * NC + col) = o0;
                }
                if (r + 8 < M) {
                    float2 o1 = make_float2(acc[mt][nt][2] + bx, acc[mt][nt][3] + by);
                    *(float2*)(C + (size_t)(r + 8) * NC + col) = o1;
                }
            }
        }
    }
}

// ---------------- fused aggregate (int16 gather) + LN + ReLU + residual ----------------
__global__ void __launch_bounds__(256)
k_agg_ln(const float* __restrict__ conv_b,
         const float* __restrict__ ln_g,
         const float* __restrict__ ln_b)
{
    int warp = (blockIdx.x * blockDim.x + threadIdx.x) >> 5;
    int lane = threadIdx.x & 31;
    if (warp >= NN) return;

    const short4* __restrict__ xq = (const short4*)g_xwq;
    int beg = g_rowptr[warp];
    int end = g_rowptr[warp + 1];

    float4 acc = make_float4(0.f, 0.f, 0.f, 0.f);
    int e = beg;
    // 8-edge unroll (MLP 16)
    for (; e + 8 <= end; e += 8) {
        int s0 = g_csr[e],     s1 = g_csr[e + 1], s2 = g_csr[e + 2], s3 = g_csr[e + 3];
        int s4 = g_csr[e + 4], s5 = g_csr[e + 5], s6 = g_csr[e + 6], s7 = g_csr[e + 7];
        float w0 = g_ws[s0], w1 = g_ws[s1], w2 = g_ws[s2], w3 = g_ws[s3];
        float w4 = g_ws[s4], w5 = g_ws[s5], w6 = g_ws[s6], w7 = g_ws[s7];
        short4 v0 = xq[s0 * 32 + lane], v1 = xq[s1 * 32 + lane];
        short4 v2 = xq[s2 * 32 + lane], v3 = xq[s3 * 32 + lane];
        short4 v4 = xq[s4 * 32 + lane], v5 = xq[s5 * 32 + lane];
        short4 v6 = xq[s6 * 32 + lane], v7 = xq[s7 * 32 + lane];
        acc.x += w0 * (float)v0.x + w1 * (float)v1.x + w2 * (float)v2.x + w3 * (float)v3.x
               + w4 * (float)v4.x + w5 * (float)v5.x + w6 * (float)v6.x + w7 * (float)v7.x;
        acc.y += w0 * (float)v0.y + w1 * (float)v1.y + w2 * (float)v2.y + w3 * (float)v3.y
               + w4 * (float)v4.y + w5 * (float)v5.y + w6 * (float)v6.y + w7 * (float)v7.y;
        acc.z += w0 * (float)v0.z + w1 * (float)v1.z + w2 * (float)v2.z + w3 * (float)v3.z
               + w4 * (float)v4.z + w5 * (float)v5.z + w6 * (float)v6.z + w7 * (float)v7.z;
        acc.w += w0 * (float)v0.w + w1 * (float)v1.w + w2 * (float)v2.w + w3 * (float)v3.w
               + w4 * (float)v4.w + w5 * (float)v5.w + w6 * (float)v6.w + w7 * (float)v7.w;
    }
    for (; e < end; e++) {
        int s = g_csr[e];
        float w = g_ws[s];
        short4 v = xq[s * 32 + lane];
        acc.x += w * (float)v.x; acc.y += w * (float)v.y;
        acc.z += w * (float)v.z; acc.w += w * (float)v.w;
    }
    // self loop
    {
        float w = g_ws[warp];
        short4 v = xq[warp * 32 + lane];
        acc.x += w * (float)v.x; acc.y += w * (float)v.y;
        acc.z += w * (float)v.z; acc.w += w * (float)v.w;
    }
    float di = g_dinv[warp];
    acc.x *= di; acc.y *= di; acc.z *= di; acc.w *= di;

    float4 cb = ((const float4*)conv_b)[lane];
    acc.x += cb.x; acc.y += cb.y; acc.z += cb.z; acc.w += cb.w;

    float s = acc.x + acc.y + acc.z + acc.w;
#pragma unroll
    for (int off = 16; off > 0; off >>= 1) s += __shfl_xor_sync(0xffffffffu, s, off);
    float mu = s * (1.f / 128.f);
    float dx = acc.x - mu, dy = acc.y - mu, dz = acc.z - mu, dw = acc.w - mu;
    float q = dx * dx + dy * dy + dz * dz + dw * dw;
#pragma unroll
    for (int off = 16; off > 0; off >>= 1) q += __shfl_xor_sync(0xffffffffu, q, off);
    float rstd = rsqrtf(q * (1.f / 128.f) + LN_EPS);

    float4 lg = ((const float4*)ln_g)[lane];
    float4 lb = ((const float4*)ln_b)[lane];
    float4 y;
    y.x = fmaxf(dx * rstd * lg.x + lb.x, 0.f);
    y.y = fmaxf(dy * rstd * lg.y + lb.y, 0.f);
    y.z = fmaxf(dz * rstd * lg.z + lb.z, 0.f);
    y.w = fmaxf(dw * rstd * lg.w + lb.w, 0.f);

    float4* h4 = (float4*)g_h + warp * 32 + lane;
    float4 hv = *h4;
    hv.x += y.x; hv.y += y.y; hv.z += y.z; hv.w += y.w;
    *h4 = hv;
}

// ---------------------------------------------------------------------
extern "C" void kernel_launch(void* const* d_in, const int* in_sizes, int n_in,
                              void* d_out, int out_size)
{
    const float* x      = (const float*)d_in[0];
    const int*   ei     = (const int*)  d_in[1];
    const float* in_W   = (const float*)d_in[2];
    const float* in_b   = (const float*)d_in[3];
    const float* conv_W = (const float*)d_in[4];
    const float* conv_b = (const float*)d_in[5];
    const float* ln_g   = (const float*)d_in[6];
    const float* ln_b   = (const float*)d_in[7];
    const float* out_W  = (const float*)d_in[8];
    const float* out_b  = (const float*)d_in[9];
    float* out = (float*)d_out;

    float* h  = nullptr;  cudaGetSymbolAddress((void**)&h,  g_h);
    __nv_bfloat16* wt = nullptr;  cudaGetSymbolAddress((void**)&wt, g_wt);

    __nv_bfloat16* wt_in   = wt;
    __nv_bfloat16* wt_conv = wt + 81920;
    __nv_bfloat16* wt_out  = wt + 81920 + 3 * 40960;

    const int TB = 256;
    int nb_scan = (NN + 1023) / 1024;
    int gb = (NN + 127) / 128;
    constexpr int SM128 = 2 * 20480 + 2 * 20480 + 2 * 16384;  // 114688
    constexpr int SM64  = 2 * 20480 + 2 * 10240 + 2 * 16384;  // 94208
    constexpr int PREP_TOT = IN_DIM * HID + 3 * HID * HID + HID * OUTD;

    cudaFuncSetAttribute(k_mma<IN_DIM, HID, false>,
                         cudaFuncAttributeMaxDynamicSharedMemorySize, SM128);
    cudaFuncSetAttribute(k_mma<HID, HID, true>,
                         cudaFuncAttributeMaxDynamicSharedMemorySize, SM128);
    cudaFuncSetAttribute(k_mma<HID, OUTD, false>,
                         cudaFuncAttributeMaxDynamicSharedMemorySize, SM64);

    // 0: merged weight prep
    k_prep_all<<<(PREP_TOT + TB - 1) / TB, TB>>>(in_W, conv_W, out_W);
    // 1-2: degree count
    k_zero <<<(NN + TB - 1) / TB, TB>>>();
    k_count<<<(EE + TB - 1) / TB, TB>>>(ei);
    // 3: input projection (profiled slot)
    k_mma<IN_DIM, HID, false><<<gb, 256, SM128>>>(x, wt_in, in_b, h, NN);
    // 4-7: scan (+dinv) and CSR fill
    k_scan1<<<nb_scan, 256>>>();
    k_scan2<<<1, 128>>>(nb_scan);
    k_scan3<<<(NN + 1 + TB - 1) / TB, TB>>>(nb_scan);
    k_fill <<<(EE + TB - 1) / TB, TB>>>(ei);

    for (int l = 0; l < LAYERS; l++) {
        k_mma<HID, HID, true><<<gb, 256, SM128>>>(h, wt_conv + (size_t)l * 40960,
                                                  nullptr, nullptr, NN);
        k_agg_ln<<<(NN * 32 + TB - 1) / TB, TB>>>(conv_b + (size_t)l * HID,
                                                  ln_g + (size_t)l * HID,
                                                  ln_b + (size_t)l * HID);
    }

    // output projection
    k_mma<HID, OUTD, false><<<gb, 256, SM64>>>(h, wt_out, out_b, out, NN);
}